// round 10
// baseline (speedup 1.0000x reference)
#include <cuda_runtime.h>
#include <cstdint>

#define T_LEN 4096
#define E_DIM 256
#define H_DIM 256
#define G_DIM 1024   // 4*H
#define L_TAGS 18
#define START_TAG 16
#define STOP_TAG 17
#define NEGV (-10000.0f)

// ---------------- device scratch (static: no allocations allowed) ----------
__device__ float g_pre[2][(size_t)T_LEN * G_DIM];   // pre-activations, fwd/bwd
__device__ float g_h[2][(size_t)T_LEN * H_DIM];     // hf / hb
__device__ float g_emit[(size_t)T_LEN * L_TAGS];    // emissions

// ---------------- small helpers -------------------------------------------
__device__ __forceinline__ unsigned long long ffma2(unsigned long long a,
                                                    unsigned long long b,
                                                    unsigned long long c) {
    unsigned long long d;
    asm("fma.rn.f32x2 %0, %1, %2, %3;" : "=l"(d) : "l"(a), "l"(b), "l"(c));
    return d;
}
__device__ __forceinline__ float2 unpackf2(unsigned long long v) {
    float2 r;
    asm("mov.b64 {%0, %1}, %2;" : "=f"(r.x), "=f"(r.y) : "l"(v));
    return r;
}
__device__ __forceinline__ float sigmoidf_(float x) {
    return __fdividef(1.0f, 1.0f + __expf(-x));
}
__device__ __forceinline__ float tanh_fast(float x) {
    float e = __expf(2.0f * x);
    return 1.0f - __fdividef(2.0f, e + 1.0f);
}
__device__ __forceinline__ uint32_t smem_u32(const void* p) {
    uint32_t a;
    asm("{ .reg .u64 t; cvta.to.shared.u64 t, %1; cvt.u32.u64 %0, t; }"
        : "=r"(a) : "l"(p));
    return a;
}
__device__ __forceinline__ uint32_t mapa_u32(uint32_t local, uint32_t rank) {
    uint32_t r;
    asm("mapa.shared::cluster.u32 %0, %1, %2;" : "=r"(r) : "r"(local), "r"(rank));
    return r;
}
__device__ __forceinline__ void mbar_init(uint32_t mbar, uint32_t count) {
    asm volatile("mbarrier.init.shared::cta.b64 [%0], %1;" :: "r"(mbar), "r"(count)
                 : "memory");
}
__device__ __forceinline__ void mbar_expect_tx(uint32_t mbar, uint32_t bytes) {
    asm volatile("mbarrier.arrive.expect_tx.shared::cta.b64 _, [%0], %1;"
                 :: "r"(mbar), "r"(bytes) : "memory");
}
// spin-then-sleep wait: one fast-path try_wait, then HW-sleep hinted loop.
__device__ __forceinline__ void mbar_wait(uint32_t mbar, uint32_t parity) {
    uint32_t done;
    asm volatile(
        "{\n\t.reg .pred P;\n\t"
        "mbarrier.try_wait.parity.acquire.cta.shared::cta.b64 P, [%1], %2;\n\t"
        "selp.b32 %0, 1, 0, P;\n\t}"
        : "=r"(done) : "r"(mbar), "r"(parity) : "memory");
    if (!done) {
        asm volatile(
            "{\n\t.reg .pred P;\n\t"
            "W_%=:\n\t"
            "mbarrier.try_wait.parity.acquire.cta.shared::cta.b64 P, [%0], %1, 0x989680;\n\t"
            "@P bra.uni D_%=;\n\t"
            "bra.uni W_%=;\n\t"
            "D_%=:\n\t}"
            :: "r"(mbar), "r"(parity) : "memory");
    }
}
__device__ __forceinline__ void st_async_b64(uint32_t addr, unsigned long long v,
                                             uint32_t mbar) {
    asm volatile(
        "st.async.shared::cluster.mbarrier::complete_tx::bytes.b64 [%0], %1, [%2];"
        :: "r"(addr), "l"(v), "r"(mbar) : "memory");
}
__device__ __forceinline__ void cp_async16(uint32_t dst, const void* src) {
    asm volatile("cp.async.ca.shared.global [%0], [%1], 16;"
                 :: "r"(dst), "l"(src) : "memory");
}

// ---------------- 1) fused gather + input GEMM -----------------------------
__global__ __launch_bounds__(256) void gemm_pre_kernel(
    const int* __restrict__ feats, const float* __restrict__ emb,
    const float* __restrict__ wih_f, const float* __restrict__ wih_b,
    const float* __restrict__ b_f, const float* __restrict__ b_b) {
    int dir = blockIdx.z;
    const float* wih  = dir ? wih_b : wih_f;
    const float* bias = dir ? b_b : b_f;
    float* out = g_pre[dir];

    int m0 = blockIdx.y * 64;
    int n0 = blockIdx.x * 64;

    __shared__ __align__(16) float As[64][68];
    __shared__ __align__(16) float Bs[64][68];
    __shared__ int fid[64];

    int tid = threadIdx.x;
    int tx = tid & 15, ty = tid >> 4;

    if (tid < 64) fid[tid] = feats[m0 + tid];
    __syncthreads();

    float acc[4][4];
#pragma unroll
    for (int i = 0; i < 4; i++)
#pragma unroll
        for (int j = 0; j < 4; j++) acc[i][j] = 0.f;

    for (int kb = 0; kb < 4; kb++) {
#pragma unroll
        for (int i = 0; i < 16; i++) {
            int idx = tid + i * 256;
            int m = idx >> 6, k = idx & 63;
            As[k][m] = emb[(size_t)fid[m] * E_DIM + kb * 64 + k];
            Bs[k][m] = wih[(size_t)(n0 + m) * E_DIM + kb * 64 + k];
        }
        __syncthreads();
#pragma unroll
        for (int k = 0; k < 64; k++) {
            float4 a4 = *(const float4*)&As[k][ty * 4];
            float4 b4 = *(const float4*)&Bs[k][tx * 4];
            float av[4] = {a4.x, a4.y, a4.z, a4.w};
            float bv[4] = {b4.x, b4.y, b4.z, b4.w};
#pragma unroll
            for (int i = 0; i < 4; i++)
#pragma unroll
                for (int j = 0; j < 4; j++) acc[i][j] += av[i] * bv[j];
        }
        __syncthreads();
    }
#pragma unroll
    for (int j = 0; j < 4; j++) {
        float bj = bias[n0 + tx * 4 + j];
#pragma unroll
        for (int i = 0; i < 4; i++)
            out[(size_t)(m0 + ty * 4 + i) * G_DIM + n0 + tx * 4 + j] =
                acc[i][j] + bj;
    }
}

// ---------------- 2) LSTM recurrence: producer-direct st.async -------------
// After the 8-lane reduce, EVERY lane of warp w holds the full gate sums of
// unit 4w+(lane>>3). All lanes compute gates (c replicated per ub-group).
// Lanes 0-15 then each ship one pair-packed b64 straight from registers to
// one (target CTA, unit pair): no staging STS, no __syncthreads, no proxy
// fence, no DMA engine. Self-delivery is loopback st.async (expect=1024B).
// WAR safety without block barriers: remote step-(s+1) writes into hsm[b]
// require ALL our step-s sends, each issued only after that warp finished
// reading hsm[b].
__global__ void __cluster_dims__(8, 1, 1) __launch_bounds__(256, 1)
lstm_cluster_kernel(const float* __restrict__ whh_f,
                    const float* __restrict__ whh_b) {
    __shared__ __align__(16) float hsm[2][288];        // 36-stride padded h
    __shared__ __align__(16) float pre_s[3][16][144];  // 16 steps x 4x36
    __shared__ __align__(8) unsigned long long mbar_sm[2];

    uint32_t rank;
    asm("mov.u32 %0, %%cluster_ctarank;" : "=r"(rank));
    int dir = blockIdx.x >> 3;

    const float* whh = dir ? whh_b : whh_f;
    const float* pre = g_pre[dir];
    float* hout = g_h[dir];

    int tid = threadIdx.x;
    int lane = tid & 31, warp = tid >> 5;       // 8 warps
    int cb = lane & 7;                          // column block [32cb,32cb+32)
    int ub = lane >> 3;                         // unit within warp (0..3)
    int unit = warp * 4 + ub;                   // local unit 0..31
    int k_unit = (int)rank * 32 + unit;         // global hidden unit

    // weights: all 4 gates of this unit, 32 cols -> 128 floats = 64 f32x2
    unsigned long long wr[4][16];
#pragma unroll
    for (int gg = 0; gg < 4; gg++) {
        const ulonglong2* wp = (const ulonglong2*)(
            whh + (size_t)(gg * 256 + k_unit) * H_DIM + cb * 32);
#pragma unroll
        for (int q = 0; q < 8; q++) {
            ulonglong2 v = wp[q];
            wr[gg][2 * q] = v.x;
            wr[gg][2 * q + 1] = v.y;
        }
    }

    for (int i = tid; i < 288; i += 256) { hsm[0][i] = 0.f; hsm[1][i] = 0.f; }

    uint32_t hbase = smem_u32(&hsm[0][0]);
    uint32_t pbase = smem_u32(&pre_s[0][0][0]);
    uint32_t mb0 = smem_u32(&mbar_sm[0]);
    uint32_t mb1 = smem_u32(&mbar_sm[1]);

    if (tid == 0) {
        mbar_init(mb0, 1);
        mbar_init(mb1, 1);
        mbar_expect_tx(mb1, 1024);   // step-0 sends (8 CTAs x 128B) -> mb1
    }

#define PRE_ISSUE(ck, ring)                                                   \
    do {                                                                      \
        _Pragma("unroll")                                                     \
        for (int pp = 0; pp < 2; pp++) {                                      \
            int idx = tid + pp * 256;                                         \
            int si_ = idx >> 5;                                               \
            int ga_ = (idx & 31) >> 3, l8_ = idx & 7;                         \
            int ss_ = (ck) * 16 + si_;                                        \
            int tt_ = dir ? (T_LEN - 1 - ss_) : ss_;                          \
            const float* src_ = pre + (size_t)tt_ * G_DIM + ga_ * 256 +       \
                                (int)rank * 32 + l8_ * 4;                     \
            uint32_t dst_ = pbase +                                           \
                (uint32_t)(((ring) * 16 + si_) * 144 + ga_ * 36 + l8_ * 4) * 4u; \
            cp_async16(dst_, src_);                                           \
        }                                                                     \
        asm volatile("cp.async.commit_group;" ::: "memory");                  \
    } while (0)

    PRE_ISSUE(0, 0);
    PRE_ISSUE(1, 1);

    // sender lanes: lane<16 of EVERY warp. lane = (ct<<1)|p: target CTA ct,
    // unit pair p (units 4*warp+2p, +2p+1). Dest float offset in target:
    // 36*rank + 4*warp + 2p (+288 for buffer 1).
    int sp = lane & 1;
    uint32_t ct = ((uint32_t)lane >> 1) & 7u;
    bool sender = (lane < 16);
    uint32_t dstA = 0, dstB = 0, mdA = 0, mdB = 0;
    if (sender) {
        uint32_t foff = 36u * rank + 4u * (uint32_t)warp + 2u * (uint32_t)sp;
        dstA = mapa_u32(hbase + foff * 4u, ct);            // buffer 0
        dstB = mapa_u32(hbase + (288u + foff) * 4u, ct);   // buffer 1
        mdA = mapa_u32(mb0, ct);
        mdB = mapa_u32(mb1, ct);
    }

    __syncthreads();
    asm volatile("barrier.cluster.arrive.aligned;" ::: "memory");
    asm volatile("barrier.cluster.wait.aligned;" ::: "memory");

    float c = 0.f;                 // cell state (replicated per ub-group)
    uint32_t par0 = 0, par1 = 0;

    for (int s = 0; s < T_LEN; s++) {
        int b = s & 1;
        int si = s & 15;
        int t = dir ? (T_LEN - 1 - s) : s;

        if (si == 0) {
            int c2 = (s >> 4) + 2;
            if (c2 < (T_LEN / 16)) {
                PRE_ISSUE(c2, c2 % 3);
                asm volatile("cp.async.wait_group 2;" ::: "memory");
            } else {
                asm volatile("cp.async.wait_group 0;" ::: "memory");
            }
            __syncthreads();
        }
        int buf = (s >> 4) % 3;

        // pre for gate cb of this unit (only cb<4 lanes add it)
        float p = (cb < 4) ? pre_s[buf][si][cb * 36 + unit] : 0.f;

        // wait until all 8 CTAs (incl self loopback) delivered step-s h
        if (s > 0) {
            if (b) { mbar_wait(mb1, par1); par1 ^= 1; }
            else   { mbar_wait(mb0, par0); par0 ^= 1; }
        }
        if (tid == 0) mbar_expect_tx(b ? mb1 : mb0, 1024);

        // matvec: 4 gate rows x 32 cols; h from hsm[b] block cb
        const ulonglong2* h2 = (const ulonglong2*)(&hsm[b][cb * 36]);
        unsigned long long a0 = 0ull, a1 = 0ull, a2 = 0ull, a3 = 0ull;
#pragma unroll
        for (int q = 0; q < 8; q++) {
            ulonglong2 hv = h2[q];
            a0 = ffma2(wr[0][2 * q], hv.x, a0);
            a1 = ffma2(wr[1][2 * q], hv.x, a1);
            a2 = ffma2(wr[2][2 * q], hv.x, a2);
            a3 = ffma2(wr[3][2 * q], hv.x, a3);
            a0 = ffma2(wr[0][2 * q + 1], hv.y, a0);
            a1 = ffma2(wr[1][2 * q + 1], hv.y, a1);
            a2 = ffma2(wr[2][2 * q + 1], hv.y, a2);
            a3 = ffma2(wr[3][2 * q + 1], hv.y, a3);
        }
        float2 f0 = unpackf2(a0), f1 = unpackf2(a1);
        float2 f2 = unpackf2(a2), f3 = unpackf2(a3);
        float s0 = f0.x + f0.y, s1 = f1.x + f1.y;
        float s2 = f2.x + f2.y, s3 = f3.x + f3.y;

        if (cb == 0) s0 += p;
        else if (cb == 1) s1 += p;
        else if (cb == 2) s2 += p;
        else if (cb == 3) s3 += p;

#pragma unroll
        for (int mk = 1; mk < 8; mk <<= 1) {
            s0 += __shfl_xor_sync(0xffffffffu, s0, mk);
            s1 += __shfl_xor_sync(0xffffffffu, s1, mk);
            s2 += __shfl_xor_sync(0xffffffffu, s2, mk);
            s3 += __shfl_xor_sync(0xffffffffu, s3, mk);
        }

        // gates in ALL lanes (c replicated across the 8 lanes of each unit)
        float ii = sigmoidf_(s0);
        float ff = sigmoidf_(s1);
        float oo = sigmoidf_(s3);
        c = ff * c + ii * tanh_fast(s2);
        float h = oo * tanh_fast(c);

        // pair-pack via shfl and ship immediately (lanes 0-15)
        float he = __shfl_sync(0xffffffffu, h, sp * 16);       // ub = 2p
        float ho = __shfl_sync(0xffffffffu, h, sp * 16 + 8);   // ub = 2p+1
        if (sender) {
            unsigned long long pv;
            asm("mov.b64 %0, {%1, %2};" : "=l"(pv) : "f"(he), "f"(ho));
            uint32_t d = b ? dstA : dstB;   // step-s output -> buffer b^1
            uint32_t m = b ? mdA : mdB;
            st_async_b64(d, pv, m);
        }
        // hout store off the critical path (one lane per unit)
        if (cb == 0) hout[(size_t)t * H_DIM + k_unit] = h;
    }

    // drain: final sends (step T-1, odd) targeted mb0; complete that phase
    mbar_wait(mb0, par0);
    asm volatile("barrier.cluster.arrive.aligned;" ::: "memory");
    asm volatile("barrier.cluster.wait.aligned;" ::: "memory");
#undef PRE_ISSUE
}

// ---------------- 3) emit: 16 timesteps per block, W_out SMEM-cached -------
__global__ __launch_bounds__(128) void emit_kernel(
    const float* __restrict__ Wout, const float* __restrict__ bout) {
    int t0 = blockIdx.x * 16;
    __shared__ float Wsm[L_TAGS * 512];     // 36 KB
    __shared__ float h[512];
    __shared__ float part[4][18];
    int tid = threadIdx.x;

    for (int i = tid; i < L_TAGS * 512; i += 128) Wsm[i] = Wout[i];

    for (int tl = 0; tl < 16; tl++) {
        int t = t0 + tl;
        __syncthreads();            // also covers Wsm on first iteration
        h[tid]       = g_h[0][(size_t)t * 256 + tid];
        h[tid + 128] = g_h[0][(size_t)t * 256 + 128 + tid];
        h[tid + 256] = g_h[1][(size_t)t * 256 + tid];
        h[tid + 384] = g_h[1][(size_t)t * 256 + 128 + tid];
        __syncthreads();

        if (tid < 72) {
            int jj = tid >> 2, q = tid & 3;
            const float* w = Wsm + jj * 512 + q * 128;
            const float* hh = h + q * 128;
            float a0 = 0.f, a1 = 0.f, a2 = 0.f, a3 = 0.f;
#pragma unroll
            for (int k = 0; k < 128; k += 4) {
                a0 += hh[k] * w[k];
                a1 += hh[k + 1] * w[k + 1];
                a2 += hh[k + 2] * w[k + 2];
                a3 += hh[k + 3] * w[k + 3];
            }
            part[q][jj] = (a0 + a1) + (a2 + a3);
        }
        __syncthreads();
        if (tid < 18)
            g_emit[(size_t)t * L_TAGS + tid] =
                part[0][tid] + part[1][tid] + part[2][tid] + part[3][tid] +
                bout[tid];
    }
}

// ---------------- 4) Viterbi + backtrack (one warp) -------------------------
__global__ void viterbi_kernel(const float* __restrict__ trans,
                               float* __restrict__ out, int write_score) {
    extern __shared__ unsigned char bp[];
    int j = threadIdx.x;
    bool act = (j < L_TAGS);

    float tcol[L_TAGS];
#pragma unroll
    for (int i = 0; i < L_TAGS; i++)
        tcol[i] = act ? trans[i * L_TAGS + j] : 0.f;

    float fv = act ? ((j == START_TAG) ? 0.f : NEGV) : -3.0e38f;
    float e = act ? g_emit[j] : 0.f;

    for (int t = 0; t < T_LEN; t++) {
        float e_next = (act && t + 1 < T_LEN)
                           ? g_emit[(size_t)(t + 1) * L_TAGS + j] : 0.f;
        // 6 independent chains of 3, merged in ascending order with strict >
        float bb[6];
        int aa[6];
#pragma unroll
        for (int ch = 0; ch < 6; ch++) { bb[ch] = -3.4e38f; aa[ch] = ch * 3; }
#pragma unroll
        for (int k = 0; k < 3; k++) {
#pragma unroll
            for (int ch = 0; ch < 6; ch++) {
                int i = ch * 3 + k;
                float sv = __shfl_sync(0xffffffffu, fv, i) + tcol[i];
                if (sv > bb[ch]) { bb[ch] = sv; aa[ch] = i; }
            }
        }
        float best = bb[0]; int arg = aa[0];
#pragma unroll
        for (int ch = 1; ch < 6; ch++)
            if (bb[ch] > best) { best = bb[ch]; arg = aa[ch]; }

        if (act) {
            bp[t * L_TAGS + j] = (unsigned char)arg;
            fv = best + e;
        }
        e = e_next;
    }

    float term = act ? (fv + trans[j * L_TAGS + STOP_TAG]) : -3.4e38f;
    int ai = j;
#pragma unroll
    for (int off = 16; off > 0; off >>= 1) {
        float ov = __shfl_xor_sync(0xffffffffu, term, off);
        int oi = __shfl_xor_sync(0xffffffffu, ai, off);
        if (ov > term || (ov == term && oi < ai)) { term = ov; ai = oi; }
    }

    if (j == 0) {
        if (write_score) out[0] = term;
        float* path = out + write_score;
        int tag = ai;
        for (int t = T_LEN - 1; t >= 0; t--) {
            path[t] = (float)tag;
            tag = bp[t * L_TAGS + tag];
        }
    }
}

// ---------------- launch ----------------------------------------------------
extern "C" void kernel_launch(void* const* d_in, const int* in_sizes, int n_in,
                              void* d_out, int out_size) {
    const int*   feats  = (const int*)d_in[0];
    const float* emb    = (const float*)d_in[1];
    const float* w_ih_f = (const float*)d_in[2];
    const float* w_hh_f = (const float*)d_in[3];
    const float* b_f    = (const float*)d_in[4];
    const float* w_ih_b = (const float*)d_in[5];
    const float* w_hh_b = (const float*)d_in[6];
    const float* b_b    = (const float*)d_in[7];
    const float* W_out  = (const float*)d_in[8];
    const float* b_out  = (const float*)d_in[9];
    const float* trans  = (const float*)d_in[10];

    dim3 gg(G_DIM / 64, T_LEN / 64, 2);
    gemm_pre_kernel<<<gg, 256>>>(feats, emb, w_ih_f, w_ih_b, b_f, b_b);

    lstm_cluster_kernel<<<16, 256>>>(w_hh_f, w_hh_b);

    emit_kernel<<<T_LEN / 16, 128>>>(W_out, b_out);

    int ws = (out_size > T_LEN) ? 1 : 0;   // layout: [path_score, path...]
    static int smem_set = 0;
    if (!smem_set) {
        cudaFuncSetAttribute(viterbi_kernel,
                             cudaFuncAttributeMaxDynamicSharedMemorySize,
                             T_LEN * L_TAGS + 1024);
        smem_set = 1;
    }
    viterbi_kernel<<<1, 32, T_LEN * L_TAGS>>>(trans, (float*)d_out, ws);
}

// round 11
// speedup vs baseline: 1.0090x; 1.0090x over previous
#include <cuda_runtime.h>
#include <cstdint>

#define T_LEN 4096
#define E_DIM 256
#define H_DIM 256
#define G_DIM 1024   // 4*H
#define L_TAGS 18
#define START_TAG 16
#define STOP_TAG 17
#define NEGV (-10000.0f)

// ---------------- device scratch (static: no allocations allowed) ----------
__device__ float g_pre[2][(size_t)T_LEN * G_DIM];   // pre-activations, fwd/bwd
__device__ float g_h[2][(size_t)T_LEN * H_DIM];     // hf / hb
__device__ float g_emit[(size_t)T_LEN * L_TAGS];    // emissions

// ---------------- small helpers -------------------------------------------
__device__ __forceinline__ unsigned long long ffma2(unsigned long long a,
                                                    unsigned long long b,
                                                    unsigned long long c) {
    unsigned long long d;
    asm("fma.rn.f32x2 %0, %1, %2, %3;" : "=l"(d) : "l"(a), "l"(b), "l"(c));
    return d;
}
__device__ __forceinline__ float2 unpackf2(unsigned long long v) {
    float2 r;
    asm("mov.b64 {%0, %1}, %2;" : "=f"(r.x), "=f"(r.y) : "l"(v));
    return r;
}
__device__ __forceinline__ float sigmoidf_(float x) {
    return __fdividef(1.0f, 1.0f + __expf(-x));
}
__device__ __forceinline__ float tanh_fast(float x) {
    float e = __expf(2.0f * x);
    return 1.0f - __fdividef(2.0f, e + 1.0f);
}
__device__ __forceinline__ uint32_t smem_u32(const void* p) {
    uint32_t a;
    asm("{ .reg .u64 t; cvta.to.shared.u64 t, %1; cvt.u32.u64 %0, t; }"
        : "=r"(a) : "l"(p));
    return a;
}
__device__ __forceinline__ uint32_t mapa_u32(uint32_t local, uint32_t rank) {
    uint32_t r;
    asm("mapa.shared::cluster.u32 %0, %1, %2;" : "=r"(r) : "r"(local), "r"(rank));
    return r;
}
__device__ __forceinline__ void mbar_init(uint32_t mbar, uint32_t count) {
    asm volatile("mbarrier.init.shared::cta.b64 [%0], %1;" :: "r"(mbar), "r"(count)
                 : "memory");
}
// remote count-arrive (release at cluster scope; payload-free signal)
__device__ __forceinline__ void mbar_arrive_remote(uint32_t mbar) {
    asm volatile("mbarrier.arrive.release.cluster.shared::cluster.b64 _, [%0];"
                 :: "r"(mbar) : "memory");
}
// spin-then-sleep wait with CLUSTER-scope acquire (pairs with remote arrives)
__device__ __forceinline__ void mbar_wait_cl(uint32_t mbar, uint32_t parity) {
    uint32_t done;
    asm volatile(
        "{\n\t.reg .pred P;\n\t"
        "mbarrier.try_wait.parity.acquire.cluster.shared::cta.b64 P, [%1], %2;\n\t"
        "selp.b32 %0, 1, 0, P;\n\t}"
        : "=r"(done) : "r"(mbar), "r"(parity) : "memory");
    if (!done) {
        asm volatile(
            "{\n\t.reg .pred P;\n\t"
            "W_%=:\n\t"
            "mbarrier.try_wait.parity.acquire.cluster.shared::cta.b64 P, [%0], %1, 0x989680;\n\t"
            "@P bra.uni D_%=;\n\t"
            "bra.uni W_%=;\n\t"
            "D_%=:\n\t}"
            :: "r"(mbar), "r"(parity) : "memory");
    }
}
__device__ __forceinline__ unsigned long long ld_cluster_b64(uint32_t a) {
    unsigned long long v;
    asm volatile("ld.shared::cluster.b64 %0, [%1];" : "=l"(v) : "r"(a)
                 : "memory");
    return v;
}
__device__ __forceinline__ void cp_async16(uint32_t dst, const void* src) {
    asm volatile("cp.async.ca.shared.global [%0], [%1], 16;"
                 :: "r"(dst), "l"(src) : "memory");
}

// ---------------- 1) fused gather + input GEMM -----------------------------
__global__ __launch_bounds__(256) void gemm_pre_kernel(
    const int* __restrict__ feats, const float* __restrict__ emb,
    const float* __restrict__ wih_f, const float* __restrict__ wih_b,
    const float* __restrict__ b_f, const float* __restrict__ b_b) {
    int dir = blockIdx.z;
    const float* wih  = dir ? wih_b : wih_f;
    const float* bias = dir ? b_b : b_f;
    float* out = g_pre[dir];

    int m0 = blockIdx.y * 64;
    int n0 = blockIdx.x * 64;

    __shared__ __align__(16) float As[64][68];
    __shared__ __align__(16) float Bs[64][68];
    __shared__ int fid[64];

    int tid = threadIdx.x;
    int tx = tid & 15, ty = tid >> 4;

    if (tid < 64) fid[tid] = feats[m0 + tid];
    __syncthreads();

    float acc[4][4];
#pragma unroll
    for (int i = 0; i < 4; i++)
#pragma unroll
        for (int j = 0; j < 4; j++) acc[i][j] = 0.f;

    for (int kb = 0; kb < 4; kb++) {
#pragma unroll
        for (int i = 0; i < 16; i++) {
            int idx = tid + i * 256;
            int m = idx >> 6, k = idx & 63;
            As[k][m] = emb[(size_t)fid[m] * E_DIM + kb * 64 + k];
            Bs[k][m] = wih[(size_t)(n0 + m) * E_DIM + kb * 64 + k];
        }
        __syncthreads();
#pragma unroll
        for (int k = 0; k < 64; k++) {
            float4 a4 = *(const float4*)&As[k][ty * 4];
            float4 b4 = *(const float4*)&Bs[k][tx * 4];
            float av[4] = {a4.x, a4.y, a4.z, a4.w};
            float bv[4] = {b4.x, b4.y, b4.z, b4.w};
#pragma unroll
            for (int i = 0; i < 4; i++)
#pragma unroll
                for (int j = 0; j < 4; j++) acc[i][j] += av[i] * bv[j];
        }
        __syncthreads();
    }
#pragma unroll
    for (int j = 0; j < 4; j++) {
        float bj = bias[n0 + tx * 4 + j];
#pragma unroll
        for (int i = 0; i < 4; i++)
            out[(size_t)(m0 + ty * 4 + i) * G_DIM + n0 + tx * 4 + j] =
                acc[i][j] + bj;
    }
}

// ---------------- 2) LSTM recurrence: signal + consumer-pull ---------------
// Per step: producers STS h into LOCAL hstage[b^1] + own hsm[b^1]; one bar;
// warp0 lanes 0-6 send ONE mbarrier.arrive.release.cluster to each peer
// (7 tiny RMWs; no data stores, no DMA engine, no proxy fence).
// Consumers: acquire-wait (count=7, auto re-arm), then 112 threads pull the
// 7 peer blocks via ld.shared::cluster.b64 (one parallel 215-cyc round),
// STS into hsm[b], bar, matvec.
__global__ void __cluster_dims__(8, 1, 1) __launch_bounds__(256, 1)
lstm_cluster_kernel(const float* __restrict__ whh_f,
                    const float* __restrict__ whh_b) {
    __shared__ __align__(16) float hsm[2][288];        // 36-stride padded h
    __shared__ __align__(16) float pre_s[3][16][144];  // 16 steps x 4x36
    __shared__ __align__(16) float hstage[2][32];      // fresh h, dbl-buffered
    __shared__ __align__(8) unsigned long long mbar_sm[2];

    uint32_t rank;
    asm("mov.u32 %0, %%cluster_ctarank;" : "=r"(rank));
    int dir = blockIdx.x >> 3;

    const float* whh = dir ? whh_b : whh_f;
    const float* pre = g_pre[dir];
    float* hout = g_h[dir];

    int tid = threadIdx.x;
    int lane = tid & 31, warp = tid >> 5;       // 8 warps
    int cb = lane & 7;                          // column block [32cb,32cb+32)
    int ub = lane >> 3;                         // unit within warp (0..3)
    int unit = warp * 4 + ub;                   // local unit 0..31
    int k_unit = (int)rank * 32 + unit;         // global hidden unit

    // weights: all 4 gates of this unit, 32 cols -> 128 floats = 64 f32x2
    unsigned long long wr[4][16];
#pragma unroll
    for (int gg = 0; gg < 4; gg++) {
        const ulonglong2* wp = (const ulonglong2*)(
            whh + (size_t)(gg * 256 + k_unit) * H_DIM + cb * 32);
#pragma unroll
        for (int q = 0; q < 8; q++) {
            ulonglong2 v = wp[q];
            wr[gg][2 * q] = v.x;
            wr[gg][2 * q + 1] = v.y;
        }
    }

    for (int i = tid; i < 288; i += 256) { hsm[0][i] = 0.f; hsm[1][i] = 0.f; }

    uint32_t pbase = smem_u32(&pre_s[0][0][0]);
    uint32_t sbase = smem_u32(&hstage[0][0]);
    uint32_t mb0 = smem_u32(&mbar_sm[0]);
    uint32_t mb1 = smem_u32(&mbar_sm[1]);

    if (tid == 0) {
        mbar_init(mb0, 7);   // 7 peer arrives per phase, auto re-arm
        mbar_init(mb1, 7);
    }

#define PRE_ISSUE(ck, ring)                                                   \
    do {                                                                      \
        _Pragma("unroll")                                                     \
        for (int pp = 0; pp < 2; pp++) {                                      \
            int idx = tid + pp * 256;                                         \
            int si_ = idx >> 5;                                               \
            int ga_ = (idx & 31) >> 3, l8_ = idx & 7;                         \
            int ss_ = (ck) * 16 + si_;                                        \
            int tt_ = dir ? (T_LEN - 1 - ss_) : ss_;                          \
            const float* src_ = pre + (size_t)tt_ * G_DIM + ga_ * 256 +       \
                                (int)rank * 32 + l8_ * 4;                     \
            uint32_t dst_ = pbase +                                           \
                (uint32_t)(((ring) * 16 + si_) * 144 + ga_ * 36 + l8_ * 4) * 4u; \
            cp_async16(dst_, src_);                                           \
        }                                                                     \
        asm volatile("cp.async.commit_group;" ::: "memory");                  \
    } while (0)

    PRE_ISSUE(0, 0);
    PRE_ISSUE(1, 1);

    // arrive targets (warp 0 lanes 0-6): peer = lane<rank ? lane : lane+1
    uint32_t arrA = 0, arrB = 0;
    bool arriver = (warp == 0 && lane < 7);
    if (arriver) {
        uint32_t peer = ((uint32_t)lane < rank) ? (uint32_t)lane
                                                : (uint32_t)lane + 1u;
        arrA = mapa_u32(mb0, peer);
        arrB = mapa_u32(mb1, peer);
    }

    // pull mapping (tid < 112): peer pi = tid>>4, 8B piece o8 = tid&15
    bool puller = (tid < 112);
    uint32_t pull0 = 0, pull1 = 0;   // remote hstage[0]/[1] addresses
    int pdst = 0;                    // local hsm float offset (b-indexed add)
    if (puller) {
        int pi = tid >> 4;
        uint32_t peer = ((uint32_t)pi < rank) ? (uint32_t)pi
                                              : (uint32_t)pi + 1u;
        int o8 = tid & 15;
        pull0 = mapa_u32(sbase + (uint32_t)(o8 * 8), peer);
        pull1 = mapa_u32(sbase + (uint32_t)(128 + o8 * 8), peer);
        pdst = 36 * (int)peer + o8 * 2;
    }

    __syncthreads();
    asm volatile("barrier.cluster.arrive.aligned;" ::: "memory");
    asm volatile("barrier.cluster.wait.aligned;" ::: "memory");

    float c = 0.f;                 // cell state (replicated per unit group)
    uint32_t par0 = 0, par1 = 0;

    for (int s = 0; s < T_LEN; s++) {
        int b = s & 1;
        int si = s & 15;
        int t = dir ? (T_LEN - 1 - s) : s;

        if (si == 0) {
            int c2 = (s >> 4) + 2;
            if (c2 < (T_LEN / 16)) {
                PRE_ISSUE(c2, c2 % 3);
                asm volatile("cp.async.wait_group 2;" ::: "memory");
            } else {
                asm volatile("cp.async.wait_group 0;" ::: "memory");
            }
            __syncthreads();
        }
        int buf = (s >> 4) % 3;

        // pre for gate cb of this unit (only cb<4 lanes add it)
        float p = (cb < 4) ? pre_s[buf][si][cb * 36 + unit] : 0.f;

        if (s > 0) {
            // wait for 7 peer arrives signaling their step-(s-1) h is ready
            if (b) { mbar_wait_cl(mb1, par1); par1 ^= 1; }
            else   { mbar_wait_cl(mb0, par0); par0 ^= 1; }
            // pull peer blocks (written into their hstage[b]) into hsm[b]
            if (puller) {
                unsigned long long v = ld_cluster_b64(b ? pull1 : pull0);
                *(unsigned long long*)&hsm[b][pdst] = v;
            }
            __syncthreads();   // pulled data visible to all warps
        }

        // matvec: 4 gate rows x 32 cols; h from hsm[b] block cb
        const ulonglong2* h2 = (const ulonglong2*)(&hsm[b][cb * 36]);
        unsigned long long a0 = 0ull, a1 = 0ull, a2 = 0ull, a3 = 0ull;
#pragma unroll
        for (int q = 0; q < 8; q++) {
            ulonglong2 hv = h2[q];
            a0 = ffma2(wr[0][2 * q], hv.x, a0);
            a1 = ffma2(wr[1][2 * q], hv.x, a1);
            a2 = ffma2(wr[2][2 * q], hv.x, a2);
            a3 = ffma2(wr[3][2 * q], hv.x, a3);
            a0 = ffma2(wr[0][2 * q + 1], hv.y, a0);
            a1 = ffma2(wr[1][2 * q + 1], hv.y, a1);
            a2 = ffma2(wr[2][2 * q + 1], hv.y, a2);
            a3 = ffma2(wr[3][2 * q + 1], hv.y, a3);
        }
        float2 f0 = unpackf2(a0), f1 = unpackf2(a1);
        float2 f2 = unpackf2(a2), f3 = unpackf2(a3);
        float s0 = f0.x + f0.y, s1 = f1.x + f1.y;
        float s2 = f2.x + f2.y, s3 = f3.x + f3.y;

        if (cb == 0) s0 += p;
        else if (cb == 1) s1 += p;
        else if (cb == 2) s2 += p;
        else if (cb == 3) s3 += p;

#pragma unroll
        for (int mk = 1; mk < 8; mk <<= 1) {
            s0 += __shfl_xor_sync(0xffffffffu, s0, mk);
            s1 += __shfl_xor_sync(0xffffffffu, s1, mk);
            s2 += __shfl_xor_sync(0xffffffffu, s2, mk);
            s3 += __shfl_xor_sync(0xffffffffu, s3, mk);
        }

        // gates at cb==0 lanes (4 per warp), one unit each
        if (cb == 0) {
            float ii = sigmoidf_(s0);
            float ff = sigmoidf_(s1);
            float oo = sigmoidf_(s3);
            c = ff * c + ii * tanh_fast(s2);
            float h = oo * tanh_fast(c);
            hstage[b ^ 1][unit] = h;                 // peers pull this
            hsm[b ^ 1][36 * (int)rank + unit] = h;   // self-delivery (local)
            hout[(size_t)t * H_DIM + k_unit] = h;    // off critical path
        }
        __syncthreads();   // hstage complete CTA-wide before signaling

        // signal all 7 peers: step-s h is pullable (release orders the bar)
        if (arriver) {
            if (b) mbar_arrive_remote(arrA);   // s odd -> consumed via mb0
            else   mbar_arrive_remote(arrB);   // s even -> consumed via mb1
        }
    }

    // drain: last signals (step T-1, odd) landed on peers' mb0; our own mb0
    // also has 7 unconsumed arrives -> absorb before the exit barrier.
    mbar_wait_cl(mb0, par0);
    asm volatile("barrier.cluster.arrive.aligned;" ::: "memory");
    asm volatile("barrier.cluster.wait.aligned;" ::: "memory");
#undef PRE_ISSUE
}

// ---------------- 3) emit: 16 timesteps per block, W_out SMEM-cached -------
__global__ __launch_bounds__(128) void emit_kernel(
    const float* __restrict__ Wout, const float* __restrict__ bout) {
    int t0 = blockIdx.x * 16;
    __shared__ float Wsm[L_TAGS * 512];     // 36 KB
    __shared__ float h[512];
    __shared__ float part[4][18];
    int tid = threadIdx.x;

    for (int i = tid; i < L_TAGS * 512; i += 128) Wsm[i] = Wout[i];

    for (int tl = 0; tl < 16; tl++) {
        int t = t0 + tl;
        __syncthreads();            // also covers Wsm on first iteration
        h[tid]       = g_h[0][(size_t)t * 256 + tid];
        h[tid + 128] = g_h[0][(size_t)t * 256 + 128 + tid];
        h[tid + 256] = g_h[1][(size_t)t * 256 + tid];
        h[tid + 384] = g_h[1][(size_t)t * 256 + 128 + tid];
        __syncthreads();

        if (tid < 72) {
            int jj = tid >> 2, q = tid & 3;
            const float* w = Wsm + jj * 512 + q * 128;
            const float* hh = h + q * 128;
            float a0 = 0.f, a1 = 0.f, a2 = 0.f, a3 = 0.f;
#pragma unroll
            for (int k = 0; k < 128; k += 4) {
                a0 += hh[k] * w[k];
                a1 += hh[k + 1] * w[k + 1];
                a2 += hh[k + 2] * w[k + 2];
                a3 += hh[k + 3] * w[k + 3];
            }
            part[q][jj] = (a0 + a1) + (a2 + a3);
        }
        __syncthreads();
        if (tid < 18)
            g_emit[(size_t)t * L_TAGS + tid] =
                part[0][tid] + part[1][tid] + part[2][tid] + part[3][tid] +
                bout[tid];
    }
}

// ---------------- 4) Viterbi + backtrack (one warp) -------------------------
__global__ void viterbi_kernel(const float* __restrict__ trans,
                               float* __restrict__ out, int write_score) {
    extern __shared__ unsigned char bp[];
    int j = threadIdx.x;
    bool act = (j < L_TAGS);

    float tcol[L_TAGS];
#pragma unroll
    for (int i = 0; i < L_TAGS; i++)
        tcol[i] = act ? trans[i * L_TAGS + j] : 0.f;

    float fv = act ? ((j == START_TAG) ? 0.f : NEGV) : -3.0e38f;
    float e = act ? g_emit[j] : 0.f;

    for (int t = 0; t < T_LEN; t++) {
        float e_next = (act && t + 1 < T_LEN)
                           ? g_emit[(size_t)(t + 1) * L_TAGS + j] : 0.f;
        // 6 independent chains of 3, merged ascending with strict >
        float bb[6];
        int aa[6];
#pragma unroll
        for (int ch = 0; ch < 6; ch++) { bb[ch] = -3.4e38f; aa[ch] = ch * 3; }
#pragma unroll
        for (int k = 0; k < 3; k++) {
#pragma unroll
            for (int ch = 0; ch < 6; ch++) {
                int i = ch * 3 + k;
                float sv = __shfl_sync(0xffffffffu, fv, i) + tcol[i];
                if (sv > bb[ch]) { bb[ch] = sv; aa[ch] = i; }
            }
        }
        float best = bb[0]; int arg = aa[0];
#pragma unroll
        for (int ch = 1; ch < 6; ch++)
            if (bb[ch] > best) { best = bb[ch]; arg = aa[ch]; }

        if (act) {
            bp[t * L_TAGS + j] = (unsigned char)arg;
            fv = best + e;
        }
        e = e_next;
    }

    float term = act ? (fv + trans[j * L_TAGS + STOP_TAG]) : -3.4e38f;
    int ai = j;
#pragma unroll
    for (int off = 16; off > 0; off >>= 1) {
        float ov = __shfl_xor_sync(0xffffffffu, term, off);
        int oi = __shfl_xor_sync(0xffffffffu, ai, off);
        if (ov > term || (ov == term && oi < ai)) { term = ov; ai = oi; }
    }

    if (j == 0) {
        if (write_score) out[0] = term;
        float* path = out + write_score;
        int tag = ai;
        for (int t = T_LEN - 1; t >= 0; t--) {
            path[t] = (float)tag;
            tag = bp[t * L_TAGS + tag];
        }
    }
}

// ---------------- launch ----------------------------------------------------
extern "C" void kernel_launch(void* const* d_in, const int* in_sizes, int n_in,
                              void* d_out, int out_size) {
    const int*   feats  = (const int*)d_in[0];
    const float* emb    = (const float*)d_in[1];
    const float* w_ih_f = (const float*)d_in[2];
    const float* w_hh_f = (const float*)d_in[3];
    const float* b_f    = (const float*)d_in[4];
    const float* w_ih_b = (const float*)d_in[5];
    const float* w_hh_b = (const float*)d_in[6];
    const float* b_b    = (const float*)d_in[7];
    const float* W_out  = (const float*)d_in[8];
    const float* b_out  = (const float*)d_in[9];
    const float* trans  = (const float*)d_in[10];

    dim3 gg(G_DIM / 64, T_LEN / 64, 2);
    gemm_pre_kernel<<<gg, 256>>>(feats, emb, w_ih_f, w_ih_b, b_f, b_b);

    lstm_cluster_kernel<<<16, 256>>>(w_hh_f, w_hh_b);

    emit_kernel<<<T_LEN / 16, 128>>>(W_out, b_out);

    int ws = (out_size > T_LEN) ? 1 : 0;   // layout: [path_score, path...]
    static int smem_set = 0;
    if (!smem_set) {
        cudaFuncSetAttribute(viterbi_kernel,
                             cudaFuncAttributeMaxDynamicSharedMemorySize,
                             T_LEN * L_TAGS + 1024);
        smem_set = 1;
    }
    viterbi_kernel<<<1, 32, T_LEN * L_TAGS>>>(trans, (float*)d_out, ws);
}

// round 12
// speedup vs baseline: 1.0678x; 1.0583x over previous
#include <cuda_runtime.h>
#include <cstdint>

#define T_LEN 4096
#define E_DIM 256
#define H_DIM 256
#define G_DIM 1024   // 4*H
#define L_TAGS 18
#define START_TAG 16
#define STOP_TAG 17
#define NEGV (-10000.0f)

// ---------------- device scratch (static: no allocations allowed) ----------
__device__ float g_pre[2][(size_t)T_LEN * G_DIM];   // pre-activations, fwd/bwd
__device__ float g_h[2][(size_t)T_LEN * H_DIM];     // hf / hb
__device__ float g_emit[(size_t)T_LEN * L_TAGS];    // emissions

// ---------------- small helpers -------------------------------------------
__device__ __forceinline__ unsigned long long ffma2(unsigned long long a,
                                                    unsigned long long b,
                                                    unsigned long long c) {
    unsigned long long d;
    asm("fma.rn.f32x2 %0, %1, %2, %3;" : "=l"(d) : "l"(a), "l"(b), "l"(c));
    return d;
}
__device__ __forceinline__ float2 unpackf2(unsigned long long v) {
    float2 r;
    asm("mov.b64 {%0, %1}, %2;" : "=f"(r.x), "=f"(r.y) : "l"(v));
    return r;
}
__device__ __forceinline__ float sigmoidf_(float x) {
    return __fdividef(1.0f, 1.0f + __expf(-x));
}
__device__ __forceinline__ float tanh_fast(float x) {
    float e = __expf(2.0f * x);
    return 1.0f - __fdividef(2.0f, e + 1.0f);
}
__device__ __forceinline__ uint32_t smem_u32(const void* p) {
    uint32_t a;
    asm("{ .reg .u64 t; cvta.to.shared.u64 t, %1; cvt.u32.u64 %0, t; }"
        : "=r"(a) : "l"(p));
    return a;
}
__device__ __forceinline__ uint32_t mapa_u32(uint32_t local, uint32_t rank) {
    uint32_t r;
    asm("mapa.shared::cluster.u32 %0, %1, %2;" : "=r"(r) : "r"(local), "r"(rank));
    return r;
}
__device__ __forceinline__ void mbar_init(uint32_t mbar, uint32_t count) {
    asm volatile("mbarrier.init.shared::cta.b64 [%0], %1;" :: "r"(mbar), "r"(count)
                 : "memory");
}
// remote count-arrive; release orders ALL of this thread's prior stores
__device__ __forceinline__ void mbar_arrive_remote(uint32_t mbar) {
    asm volatile("mbarrier.arrive.release.cluster.shared::cluster.b64 _, [%0];"
                 :: "r"(mbar) : "memory");
}
// spin-then-sleep wait with CLUSTER-scope acquire (pairs with remote arrives)
__device__ __forceinline__ void mbar_wait_cl(uint32_t mbar, uint32_t parity) {
    uint32_t done;
    asm volatile(
        "{\n\t.reg .pred P;\n\t"
        "mbarrier.try_wait.parity.acquire.cluster.shared::cta.b64 P, [%1], %2;\n\t"
        "selp.b32 %0, 1, 0, P;\n\t}"
        : "=r"(done) : "r"(mbar), "r"(parity) : "memory");
    if (!done) {
        asm volatile(
            "{\n\t.reg .pred P;\n\t"
            "W_%=:\n\t"
            "mbarrier.try_wait.parity.acquire.cluster.shared::cta.b64 P, [%0], %1, 0x989680;\n\t"
            "@P bra.uni D_%=;\n\t"
            "bra.uni W_%=;\n\t"
            "D_%=:\n\t}"
            :: "r"(mbar), "r"(parity) : "memory");
    }
}
// plain 16B store into a peer CTA's SMEM (generic LSU path, no DMA engine)
__device__ __forceinline__ void st_cluster_16B(uint32_t addr,
                                               unsigned long long x,
                                               unsigned long long y) {
    asm volatile("st.shared::cluster.v2.u64 [%0], {%1, %2};"
                 :: "r"(addr), "l"(x), "l"(y) : "memory");
}
__device__ __forceinline__ void cp_async16(uint32_t dst, const void* src) {
    asm volatile("cp.async.ca.shared.global [%0], [%1], 16;"
                 :: "r"(dst), "l"(src) : "memory");
}

// ---------------- 1) fused gather + input GEMM -----------------------------
__global__ __launch_bounds__(256) void gemm_pre_kernel(
    const int* __restrict__ feats, const float* __restrict__ emb,
    const float* __restrict__ wih_f, const float* __restrict__ wih_b,
    const float* __restrict__ b_f, const float* __restrict__ b_b) {
    int dir = blockIdx.z;
    const float* wih  = dir ? wih_b : wih_f;
    const float* bias = dir ? b_b : b_f;
    float* out = g_pre[dir];

    int m0 = blockIdx.y * 64;
    int n0 = blockIdx.x * 64;

    __shared__ __align__(16) float As[64][68];
    __shared__ __align__(16) float Bs[64][68];
    __shared__ int fid[64];

    int tid = threadIdx.x;
    int tx = tid & 15, ty = tid >> 4;

    if (tid < 64) fid[tid] = feats[m0 + tid];
    __syncthreads();

    float acc[4][4];
#pragma unroll
    for (int i = 0; i < 4; i++)
#pragma unroll
        for (int j = 0; j < 4; j++) acc[i][j] = 0.f;

    for (int kb = 0; kb < 4; kb++) {
#pragma unroll
        for (int i = 0; i < 16; i++) {
            int idx = tid + i * 256;
            int m = idx >> 6, k = idx & 63;
            As[k][m] = emb[(size_t)fid[m] * E_DIM + kb * 64 + k];
            Bs[k][m] = wih[(size_t)(n0 + m) * E_DIM + kb * 64 + k];
        }
        __syncthreads();
#pragma unroll
        for (int k = 0; k < 64; k++) {
            float4 a4 = *(const float4*)&As[k][ty * 4];
            float4 b4 = *(const float4*)&Bs[k][tx * 4];
            float av[4] = {a4.x, a4.y, a4.z, a4.w};
            float bv[4] = {b4.x, b4.y, b4.z, b4.w};
#pragma unroll
            for (int i = 0; i < 4; i++)
#pragma unroll
                for (int j = 0; j < 4; j++) acc[i][j] += av[i] * bv[j];
        }
        __syncthreads();
    }
#pragma unroll
    for (int j = 0; j < 4; j++) {
        float bj = bias[n0 + tx * 4 + j];
#pragma unroll
        for (int i = 0; i < 4; i++)
            out[(size_t)(m0 + ty * 4 + i) * G_DIM + n0 + tx * 4 + j] =
                acc[i][j] + bj;
    }
}

// ---------------- 2) LSTM recurrence: plain-store push + arrive-release ----
// R9 structure with the send path swapped: warp 0 lanes 0-7 each push the
// CTA's 128B h block to one target CTA via 8 plain 16B cluster stores, then
// ONE mbarrier.arrive.release.cluster (orders that lane's stores). One
// crossing, 8 msgs, 8 RMWs, no DMA engine, no proxy fence, no expect_tx.
__global__ void __cluster_dims__(8, 1, 1) __launch_bounds__(256, 1)
lstm_cluster_kernel(const float* __restrict__ whh_f,
                    const float* __restrict__ whh_b) {
    __shared__ __align__(16) float hsm[2][288];        // 36-stride padded h
    __shared__ __align__(16) float pre_s[3][16][144];  // 16 steps x 4x36
    __shared__ __align__(16) float hstage[2][32];      // fresh h, dbl-buffered
    __shared__ __align__(8) unsigned long long mbar_sm[2];

    uint32_t rank;
    asm("mov.u32 %0, %%cluster_ctarank;" : "=r"(rank));
    int dir = blockIdx.x >> 3;

    const float* whh = dir ? whh_b : whh_f;
    const float* pre = g_pre[dir];
    float* hout = g_h[dir];

    int tid = threadIdx.x;
    int lane = tid & 31, warp = tid >> 5;       // 8 warps
    int cb = lane & 7;                          // column block [32cb,32cb+32)
    int ub = lane >> 3;                         // unit within warp (0..3)
    int unit = warp * 4 + ub;                   // local unit 0..31
    int k_unit = (int)rank * 32 + unit;         // global hidden unit

    // weights: all 4 gates of this unit, 32 cols -> 128 floats = 64 f32x2
    unsigned long long wr[4][16];
#pragma unroll
    for (int gg = 0; gg < 4; gg++) {
        const ulonglong2* wp = (const ulonglong2*)(
            whh + (size_t)(gg * 256 + k_unit) * H_DIM + cb * 32);
#pragma unroll
        for (int q = 0; q < 8; q++) {
            ulonglong2 v = wp[q];
            wr[gg][2 * q] = v.x;
            wr[gg][2 * q + 1] = v.y;
        }
    }

    for (int i = tid; i < 288; i += 256) { hsm[0][i] = 0.f; hsm[1][i] = 0.f; }

    uint32_t hbase = smem_u32(&hsm[0][0]);
    uint32_t pbase = smem_u32(&pre_s[0][0][0]);
    uint32_t mb0 = smem_u32(&mbar_sm[0]);
    uint32_t mb1 = smem_u32(&mbar_sm[1]);

    if (tid == 0) {
        mbar_init(mb0, 8);   // 8 source-CTA arrives per phase, auto re-arm
        mbar_init(mb1, 8);
    }

#define PRE_ISSUE(ck, ring)                                                   \
    do {                                                                      \
        _Pragma("unroll")                                                     \
        for (int pp = 0; pp < 2; pp++) {                                      \
            int idx = tid + pp * 256;                                         \
            int si_ = idx >> 5;                                               \
            int ga_ = (idx & 31) >> 3, l8_ = idx & 7;                         \
            int ss_ = (ck) * 16 + si_;                                        \
            int tt_ = dir ? (T_LEN - 1 - ss_) : ss_;                          \
            const float* src_ = pre + (size_t)tt_ * G_DIM + ga_ * 256 +       \
                                (int)rank * 32 + l8_ * 4;                     \
            uint32_t dst_ = pbase +                                           \
                (uint32_t)(((ring) * 16 + si_) * 144 + ga_ * 36 + l8_ * 4) * 4u; \
            cp_async16(dst_, src_);                                           \
        }                                                                     \
        asm volatile("cp.async.commit_group;" ::: "memory");                  \
    } while (0)

    PRE_ISSUE(0, 0);
    PRE_ISSUE(1, 1);

    // sender setup (warp 0 lanes 0-7, incl self loopback): this CTA's 32 h
    // land at float offset 36*rank (buffer 0) / 288+36*rank (buffer 1) in
    // every CTA's hsm.
    uint32_t dstA = 0, dstB = 0, mdA = 0, mdB = 0;
    bool sender = (warp == 0 && lane < 8);
    if (sender) {
        dstA = mapa_u32(hbase + (uint32_t)(36 * rank) * 4u, (uint32_t)lane);
        dstB = mapa_u32(hbase + (uint32_t)(288 + 36 * rank) * 4u, (uint32_t)lane);
        mdA = mapa_u32(mb0, (uint32_t)lane);
        mdB = mapa_u32(mb1, (uint32_t)lane);
    }

    __syncthreads();
    asm volatile("barrier.cluster.arrive.aligned;" ::: "memory");
    asm volatile("barrier.cluster.wait.aligned;" ::: "memory");

    float c = 0.f;                 // cell state at cb==0 lanes
    uint32_t par0 = 0, par1 = 0;

    for (int s = 0; s < T_LEN; s++) {
        int b = s & 1;
        int si = s & 15;
        int t = dir ? (T_LEN - 1 - s) : s;

        if (si == 0) {
            int c2 = (s >> 4) + 2;
            if (c2 < (T_LEN / 16)) {
                PRE_ISSUE(c2, c2 % 3);
                asm volatile("cp.async.wait_group 2;" ::: "memory");
            } else {
                asm volatile("cp.async.wait_group 0;" ::: "memory");
            }
            __syncthreads();
        }
        int buf = (s >> 4) % 3;

        // pre for gate cb of this unit (only cb<4 lanes add it)
        float p = (cb < 4) ? pre_s[buf][si][cb * 36 + unit] : 0.f;

        // wait until all 8 source CTAs delivered + signaled step-(s-1) h
        if (s > 0) {
            if (b) { mbar_wait_cl(mb1, par1); par1 ^= 1; }
            else   { mbar_wait_cl(mb0, par0); par0 ^= 1; }
        }

        // matvec: 4 gate rows x 32 cols; h from hsm[b] block cb
        const ulonglong2* h2 = (const ulonglong2*)(&hsm[b][cb * 36]);
        unsigned long long a0 = 0ull, a1 = 0ull, a2 = 0ull, a3 = 0ull;
#pragma unroll
        for (int q = 0; q < 8; q++) {
            ulonglong2 hv = h2[q];
            a0 = ffma2(wr[0][2 * q], hv.x, a0);
            a1 = ffma2(wr[1][2 * q], hv.x, a1);
            a2 = ffma2(wr[2][2 * q], hv.x, a2);
            a3 = ffma2(wr[3][2 * q], hv.x, a3);
            a0 = ffma2(wr[0][2 * q + 1], hv.y, a0);
            a1 = ffma2(wr[1][2 * q + 1], hv.y, a1);
            a2 = ffma2(wr[2][2 * q + 1], hv.y, a2);
            a3 = ffma2(wr[3][2 * q + 1], hv.y, a3);
        }
        float2 f0 = unpackf2(a0), f1 = unpackf2(a1);
        float2 f2 = unpackf2(a2), f3 = unpackf2(a3);
        float s0 = f0.x + f0.y, s1 = f1.x + f1.y;
        float s2 = f2.x + f2.y, s3 = f3.x + f3.y;

        if (cb == 0) s0 += p;
        else if (cb == 1) s1 += p;
        else if (cb == 2) s2 += p;
        else if (cb == 3) s3 += p;

#pragma unroll
        for (int mk = 1; mk < 8; mk <<= 1) {
            s0 += __shfl_xor_sync(0xffffffffu, s0, mk);
            s1 += __shfl_xor_sync(0xffffffffu, s1, mk);
            s2 += __shfl_xor_sync(0xffffffffu, s2, mk);
            s3 += __shfl_xor_sync(0xffffffffu, s3, mk);
        }

        // gates at cb==0 lanes (4 per warp), one unit each
        if (cb == 0) {
            float ii = sigmoidf_(s0);
            float ff = sigmoidf_(s1);
            float oo = sigmoidf_(s3);
            c = ff * c + ii * tanh_fast(s2);
            float h = oo * tanh_fast(c);
            hstage[b ^ 1][unit] = h;
            hout[(size_t)t * H_DIM + k_unit] = h;   // off critical path
        }
        __syncthreads();   // hstage complete; all hsm[b] reads retired

        // warp 0 lanes 0-7: push 128B to CTA 'lane' + one release-arrive
        if (sender) {
            const ulonglong2* st2 =
                (const ulonglong2*)&hstage[b ^ 1][0];
            uint32_t d = b ? dstA : dstB;   // step-s output -> buffer b^1
#pragma unroll
            for (int q = 0; q < 8; q++) {
                ulonglong2 x = st2[q];      // broadcast LDS.128
                st_cluster_16B(d + (uint32_t)q * 16u, x.x, x.y);
            }
            mbar_arrive_remote(b ? mdA : mdB);
        }
    }

    // drain: final sends (step T-1, odd) arrived on mb0; absorb that phase
    mbar_wait_cl(mb0, par0);
    asm volatile("barrier.cluster.arrive.aligned;" ::: "memory");
    asm volatile("barrier.cluster.wait.aligned;" ::: "memory");
#undef PRE_ISSUE
}

// ---------------- 3) emit: 16 timesteps per block, W_out SMEM-cached -------
__global__ __launch_bounds__(128) void emit_kernel(
    const float* __restrict__ Wout, const float* __restrict__ bout) {
    int t0 = blockIdx.x * 16;
    __shared__ float Wsm[L_TAGS * 512];     // 36 KB
    __shared__ float h[512];
    __shared__ float part[4][18];
    int tid = threadIdx.x;

    for (int i = tid; i < L_TAGS * 512; i += 128) Wsm[i] = Wout[i];

    for (int tl = 0; tl < 16; tl++) {
        int t = t0 + tl;
        __syncthreads();            // also covers Wsm on first iteration
        h[tid]       = g_h[0][(size_t)t * 256 + tid];
        h[tid + 128] = g_h[0][(size_t)t * 256 + 128 + tid];
        h[tid + 256] = g_h[1][(size_t)t * 256 + tid];
        h[tid + 384] = g_h[1][(size_t)t * 256 + 128 + tid];
        __syncthreads();

        if (tid < 72) {
            int jj = tid >> 2, q = tid & 3;
            const float* w = Wsm + jj * 512 + q * 128;
            const float* hh = h + q * 128;
            float a0 = 0.f, a1 = 0.f, a2 = 0.f, a3 = 0.f;
#pragma unroll
            for (int k = 0; k < 128; k += 4) {
                a0 += hh[k] * w[k];
                a1 += hh[k + 1] * w[k + 1];
                a2 += hh[k + 2] * w[k + 2];
                a3 += hh[k + 3] * w[k + 3];
            }
            part[q][jj] = (a0 + a1) + (a2 + a3);
        }
        __syncthreads();
        if (tid < 18)
            g_emit[(size_t)t * L_TAGS + tid] =
                part[0][tid] + part[1][tid] + part[2][tid] + part[3][tid] +
                bout[tid];
    }
}

// ---------------- 4) Viterbi + backtrack (one warp) -------------------------
__global__ void viterbi_kernel(const float* __restrict__ trans,
                               float* __restrict__ out, int write_score) {
    extern __shared__ unsigned char bp[];
    int j = threadIdx.x;
    bool act = (j < L_TAGS);

    float tcol[L_TAGS];
#pragma unroll
    for (int i = 0; i < L_TAGS; i++)
        tcol[i] = act ? trans[i * L_TAGS + j] : 0.f;

    float fv = act ? ((j == START_TAG) ? 0.f : NEGV) : -3.0e38f;
    float e = act ? g_emit[j] : 0.f;

    for (int t = 0; t < T_LEN; t++) {
        float e_next = (act && t + 1 < T_LEN)
                           ? g_emit[(size_t)(t + 1) * L_TAGS + j] : 0.f;
        // 6 independent chains of 3, merged ascending with strict >
        float bb[6];
        int aa[6];
#pragma unroll
        for (int ch = 0; ch < 6; ch++) { bb[ch] = -3.4e38f; aa[ch] = ch * 3; }
#pragma unroll
        for (int k = 0; k < 3; k++) {
#pragma unroll
            for (int ch = 0; ch < 6; ch++) {
                int i = ch * 3 + k;
                float sv = __shfl_sync(0xffffffffu, fv, i) + tcol[i];
                if (sv > bb[ch]) { bb[ch] = sv; aa[ch] = i; }
            }
        }
        float best = bb[0]; int arg = aa[0];
#pragma unroll
        for (int ch = 1; ch < 6; ch++)
            if (bb[ch] > best) { best = bb[ch]; arg = aa[ch]; }

        if (act) {
            bp[t * L_TAGS + j] = (unsigned char)arg;
            fv = best + e;
        }
        e = e_next;
    }

    float term = act ? (fv + trans[j * L_TAGS + STOP_TAG]) : -3.4e38f;
    int ai = j;
#pragma unroll
    for (int off = 16; off > 0; off >>= 1) {
        float ov = __shfl_xor_sync(0xffffffffu, term, off);
        int oi = __shfl_xor_sync(0xffffffffu, ai, off);
        if (ov > term || (ov == term && oi < ai)) { term = ov; ai = oi; }
    }

    if (j == 0) {
        if (write_score) out[0] = term;
        float* path = out + write_score;
        int tag = ai;
        for (int t = T_LEN - 1; t >= 0; t--) {
            path[t] = (float)tag;
            tag = bp[t * L_TAGS + tag];
        }
    }
}

// ---------------- launch ----------------------------------------------------
extern "C" void kernel_launch(void* const* d_in, const int* in_sizes, int n_in,
                              void* d_out, int out_size) {
    const int*   feats  = (const int*)d_in[0];
    const float* emb    = (const float*)d_in[1];
    const float* w_ih_f = (const float*)d_in[2];
    const float* w_hh_f = (const float*)d_in[3];
    const float* b_f    = (const float*)d_in[4];
    const float* w_ih_b = (const float*)d_in[5];
    const float* w_hh_b = (const float*)d_in[6];
    const float* b_b    = (const float*)d_in[7];
    const float* W_out  = (const float*)d_in[8];
    const float* b_out  = (const float*)d_in[9];
    const float* trans  = (const float*)d_in[10];

    dim3 gg(G_DIM / 64, T_LEN / 64, 2);
    gemm_pre_kernel<<<gg, 256>>>(feats, emb, w_ih_f, w_ih_b, b_f, b_b);

    lstm_cluster_kernel<<<16, 256>>>(w_hh_f, w_hh_b);

    emit_kernel<<<T_LEN / 16, 128>>>(W_out, b_out);

    int ws = (out_size > T_LEN) ? 1 : 0;   // layout: [path_score, path...]
    static int smem_set = 0;
    if (!smem_set) {
        cudaFuncSetAttribute(viterbi_kernel,
                             cudaFuncAttributeMaxDynamicSharedMemorySize,
                             T_LEN * L_TAGS + 1024);
        smem_set = 1;
    }
    viterbi_kernel<<<1, 32, T_LEN * L_TAGS>>>(trans, (float*)d_out, ws);
}

// round 13
// speedup vs baseline: 1.3070x; 1.2240x over previous
#include <cuda_runtime.h>
#include <cstdint>

#define T_LEN 4096
#define E_DIM 256
#define H_DIM 256
#define G_DIM 1024   // 4*H
#define L_TAGS 18
#define START_TAG 16
#define STOP_TAG 17
#define NEGV (-10000.0f)

// ---------------- device scratch (static: no allocations allowed) ----------
__device__ float g_pre[2][(size_t)T_LEN * G_DIM];   // pre-activations, fwd/bwd
__device__ float g_h[2][(size_t)T_LEN * H_DIM];     // hf / hb
__device__ float g_emit[(size_t)T_LEN * L_TAGS];    // emissions

// ---------------- small helpers -------------------------------------------
__device__ __forceinline__ unsigned long long ffma2(unsigned long long a,
                                                    unsigned long long b,
                                                    unsigned long long c) {
    unsigned long long d;
    asm("fma.rn.f32x2 %0, %1, %2, %3;" : "=l"(d) : "l"(a), "l"(b), "l"(c));
    return d;
}
__device__ __forceinline__ float2 unpackf2(unsigned long long v) {
    float2 r;
    asm("mov.b64 {%0, %1}, %2;" : "=f"(r.x), "=f"(r.y) : "l"(v));
    return r;
}
__device__ __forceinline__ float sigmoidf_(float x) {
    return __fdividef(1.0f, 1.0f + __expf(-x));
}
__device__ __forceinline__ float tanh_fast(float x) {
    float e = __expf(2.0f * x);
    return 1.0f - __fdividef(2.0f, e + 1.0f);
}
__device__ __forceinline__ uint32_t smem_u32(const void* p) {
    uint32_t a;
    asm("{ .reg .u64 t; cvta.to.shared.u64 t, %1; cvt.u32.u64 %0, t; }"
        : "=r"(a) : "l"(p));
    return a;
}
__device__ __forceinline__ uint32_t mapa_u32(uint32_t local, uint32_t rank) {
    uint32_t r;
    asm("mapa.shared::cluster.u32 %0, %1, %2;" : "=r"(r) : "r"(local), "r"(rank));
    return r;
}
__device__ __forceinline__ void mbar_init(uint32_t mbar, uint32_t count) {
    asm volatile("mbarrier.init.shared::cta.b64 [%0], %1;" :: "r"(mbar), "r"(count)
                 : "memory");
}
__device__ __forceinline__ void mbar_expect_tx(uint32_t mbar, uint32_t bytes) {
    asm volatile("mbarrier.arrive.expect_tx.shared::cta.b64 _, [%0], %1;"
                 :: "r"(mbar), "r"(bytes) : "memory");
}
// spin-then-sleep wait: one fast-path try_wait, then HW-sleep hinted loop.
__device__ __forceinline__ void mbar_wait(uint32_t mbar, uint32_t parity) {
    uint32_t done;
    asm volatile(
        "{\n\t.reg .pred P;\n\t"
        "mbarrier.try_wait.parity.acquire.cta.shared::cta.b64 P, [%1], %2;\n\t"
        "selp.b32 %0, 1, 0, P;\n\t}"
        : "=r"(done) : "r"(mbar), "r"(parity) : "memory");
    if (!done) {
        asm volatile(
            "{\n\t.reg .pred P;\n\t"
            "W_%=:\n\t"
            "mbarrier.try_wait.parity.acquire.cta.shared::cta.b64 P, [%0], %1, 0x989680;\n\t"
            "@P bra.uni D_%=;\n\t"
            "bra.uni W_%=;\n\t"
            "D_%=:\n\t}"
            :: "r"(mbar), "r"(parity) : "memory");
    }
}
// one-shot 128B SMEM -> remote-CTA SMEM with single tx update on remote mbar
__device__ __forceinline__ void bulk_s2cluster(uint32_t dst, uint32_t src,
                                               uint32_t bytes, uint32_t rmbar) {
    asm volatile(
        "cp.async.bulk.shared::cluster.shared::cta.mbarrier::complete_tx::bytes "
        "[%0], [%1], %2, [%3];"
        :: "r"(dst), "r"(src), "r"(bytes), "r"(rmbar) : "memory");
}
__device__ __forceinline__ void cp_async16(uint32_t dst, const void* src) {
    asm volatile("cp.async.ca.shared.global [%0], [%1], 16;"
                 :: "r"(dst), "l"(src) : "memory");
}

// ---------------- 1) fused gather + input GEMM -----------------------------
__global__ __launch_bounds__(256) void gemm_pre_kernel(
    const int* __restrict__ feats, const float* __restrict__ emb,
    const float* __restrict__ wih_f, const float* __restrict__ wih_b,
    const float* __restrict__ b_f, const float* __restrict__ b_b) {
    int dir = blockIdx.z;
    const float* wih  = dir ? wih_b : wih_f;
    const float* bias = dir ? b_b : b_f;
    float* out = g_pre[dir];

    int m0 = blockIdx.y * 64;
    int n0 = blockIdx.x * 64;

    __shared__ __align__(16) float As[64][68];
    __shared__ __align__(16) float Bs[64][68];
    __shared__ int fid[64];

    int tid = threadIdx.x;
    int tx = tid & 15, ty = tid >> 4;

    if (tid < 64) fid[tid] = feats[m0 + tid];
    __syncthreads();

    float acc[4][4];
#pragma unroll
    for (int i = 0; i < 4; i++)
#pragma unroll
        for (int j = 0; j < 4; j++) acc[i][j] = 0.f;

    for (int kb = 0; kb < 4; kb++) {
#pragma unroll
        for (int i = 0; i < 16; i++) {
            int idx = tid + i * 256;
            int m = idx >> 6, k = idx & 63;
            As[k][m] = emb[(size_t)fid[m] * E_DIM + kb * 64 + k];
            Bs[k][m] = wih[(size_t)(n0 + m) * E_DIM + kb * 64 + k];
        }
        __syncthreads();
#pragma unroll
        for (int k = 0; k < 64; k++) {
            float4 a4 = *(const float4*)&As[k][ty * 4];
            float4 b4 = *(const float4*)&Bs[k][tx * 4];
            float av[4] = {a4.x, a4.y, a4.z, a4.w};
            float bv[4] = {b4.x, b4.y, b4.z, b4.w};
#pragma unroll
            for (int i = 0; i < 4; i++)
#pragma unroll
                for (int j = 0; j < 4; j++) acc[i][j] += av[i] * bv[j];
        }
        __syncthreads();
    }
#pragma unroll
    for (int j = 0; j < 4; j++) {
        float bj = bias[n0 + tx * 4 + j];
#pragma unroll
        for (int i = 0; i < 4; i++)
            out[(size_t)(m0 + ty * 4 + i) * G_DIM + n0 + tx * 4 + j] =
                acc[i][j] + bj;
    }
}

// ---------------- 2) LSTM recurrence: R9 comm (bulk x7) + micro-trims ------
// Changes vs R9: pre ring-of-4 (power-of-2 modulo, 3 chunks in flight),
// hstage removed (bulk sends source directly from hsm self-block).
__global__ void __cluster_dims__(8, 1, 1) __launch_bounds__(256, 1)
lstm_cluster_kernel(const float* __restrict__ whh_f,
                    const float* __restrict__ whh_b) {
    __shared__ __align__(16) float hsm[2][288];        // 36-stride padded h
    __shared__ __align__(16) float pre_s[4][16][144];  // ring-4: 16 steps x 4x36
    __shared__ __align__(8) unsigned long long mbar_sm[2];

    uint32_t rank;
    asm("mov.u32 %0, %%cluster_ctarank;" : "=r"(rank));
    int dir = blockIdx.x >> 3;

    const float* whh = dir ? whh_b : whh_f;
    const float* pre = g_pre[dir];
    float* hout = g_h[dir];

    int tid = threadIdx.x;
    int lane = tid & 31, warp = tid >> 5;       // 8 warps
    int cb = lane & 7;                          // column block [32cb,32cb+32)
    int ub = lane >> 3;                         // unit within warp (0..3)
    int unit = warp * 4 + ub;                   // local unit 0..31
    int k_unit = (int)rank * 32 + unit;         // global hidden unit

    // weights: all 4 gates of this unit, 32 cols -> 128 floats = 64 f32x2
    unsigned long long wr[4][16];
#pragma unroll
    for (int gg = 0; gg < 4; gg++) {
        const ulonglong2* wp = (const ulonglong2*)(
            whh + (size_t)(gg * 256 + k_unit) * H_DIM + cb * 32);
#pragma unroll
        for (int q = 0; q < 8; q++) {
            ulonglong2 v = wp[q];
            wr[gg][2 * q] = v.x;
            wr[gg][2 * q + 1] = v.y;
        }
    }

    for (int i = tid; i < 288; i += 256) { hsm[0][i] = 0.f; hsm[1][i] = 0.f; }

    uint32_t hbase = smem_u32(&hsm[0][0]);
    uint32_t pbase = smem_u32(&pre_s[0][0][0]);
    uint32_t mb0 = smem_u32(&mbar_sm[0]);
    uint32_t mb1 = smem_u32(&mbar_sm[1]);

    if (tid == 0) {
        mbar_init(mb0, 1);
        mbar_init(mb1, 1);
        mbar_expect_tx(mb1, 896);    // step-0 sends (7 peers x 128B) -> mb1
    }

#define PRE_ISSUE(ck)                                                         \
    do {                                                                      \
        _Pragma("unroll")                                                     \
        for (int pp = 0; pp < 2; pp++) {                                      \
            int idx = tid + pp * 256;                                         \
            int si_ = idx >> 5;                                               \
            int ga_ = (idx & 31) >> 3, l8_ = idx & 7;                         \
            int ss_ = (ck) * 16 + si_;                                        \
            int tt_ = dir ? (T_LEN - 1 - ss_) : ss_;                          \
            const float* src_ = pre + (size_t)tt_ * G_DIM + ga_ * 256 +       \
                                (int)rank * 32 + l8_ * 4;                     \
            uint32_t dst_ = pbase +                                           \
                (uint32_t)((((ck) & 3) * 16 + si_) * 144 + ga_ * 36 +         \
                           l8_ * 4) * 4u;                                     \
            cp_async16(dst_, src_);                                           \
        }                                                                     \
        asm volatile("cp.async.commit_group;" ::: "memory");                  \
    } while (0)

    PRE_ISSUE(0);
    PRE_ISSUE(1);
    PRE_ISSUE(2);

    // sender setup (warp 0 lanes 0-7, skipping self): source = hsm self block
    // at float offset 36*rank (buffer0) / 288+36*rank (buffer1).
    uint32_t dst_b0 = 0, dst_b1 = 0, mdst0 = 0, mdst1 = 0;
    bool sender = (warp == 0 && lane < 8 && (uint32_t)lane != rank);
    uint32_t src_b0 = hbase + (uint32_t)(36 * rank) * 4u;
    uint32_t src_b1 = hbase + (uint32_t)(288 + 36 * rank) * 4u;
    if (warp == 0 && lane < 8) {
        dst_b0 = mapa_u32(src_b0, (uint32_t)lane);
        dst_b1 = mapa_u32(src_b1, (uint32_t)lane);
        mdst0 = mapa_u32(mb0, (uint32_t)lane);
        mdst1 = mapa_u32(mb1, (uint32_t)lane);
    }

    __syncthreads();
    asm volatile("barrier.cluster.arrive.aligned;" ::: "memory");
    asm volatile("barrier.cluster.wait.aligned;" ::: "memory");

    float c = 0.f;                 // cell state at cb==0 lanes
    uint32_t par0 = 0, par1 = 0;

    for (int s = 0; s < T_LEN; s++) {
        int b = s & 1;
        int si = s & 15;
        int t = dir ? (T_LEN - 1 - s) : s;

        if (si == 0) {
            int c3 = (s >> 4) + 3;
            if (c3 < (T_LEN / 16)) {
                PRE_ISSUE(c3);
                asm volatile("cp.async.wait_group 2;" ::: "memory");
            } else {
                asm volatile("cp.async.wait_group 0;" ::: "memory");
            }
            __syncthreads();
        }
        int buf = (s >> 4) & 3;

        // pre for gate cb of this unit (only cb<4 lanes add it)
        float p = (cb < 4) ? pre_s[buf][si][cb * 36 + unit] : 0.f;

        // wait until all 7 remote CTAs delivered h for this step
        if (s > 0) {
            if (b) { mbar_wait(mb1, par1); par1 ^= 1; }
            else   { mbar_wait(mb0, par0); par0 ^= 1; }
        }
        if (tid == 0) mbar_expect_tx(b ? mb1 : mb0, 896);

        // matvec: 4 gate rows x 32 cols; h from hsm[b] block cb
        const ulonglong2* h2 = (const ulonglong2*)(&hsm[b][cb * 36]);
        unsigned long long a0 = 0ull, a1 = 0ull, a2 = 0ull, a3 = 0ull;
#pragma unroll
        for (int q = 0; q < 8; q++) {
            ulonglong2 hv = h2[q];
            a0 = ffma2(wr[0][2 * q], hv.x, a0);
            a1 = ffma2(wr[1][2 * q], hv.x, a1);
            a2 = ffma2(wr[2][2 * q], hv.x, a2);
            a3 = ffma2(wr[3][2 * q], hv.x, a3);
            a0 = ffma2(wr[0][2 * q + 1], hv.y, a0);
            a1 = ffma2(wr[1][2 * q + 1], hv.y, a1);
            a2 = ffma2(wr[2][2 * q + 1], hv.y, a2);
            a3 = ffma2(wr[3][2 * q + 1], hv.y, a3);
        }
        float2 f0 = unpackf2(a0), f1 = unpackf2(a1);
        float2 f2 = unpackf2(a2), f3 = unpackf2(a3);
        float s0 = f0.x + f0.y, s1 = f1.x + f1.y;
        float s2 = f2.x + f2.y, s3 = f3.x + f3.y;

        if (cb == 0) s0 += p;
        else if (cb == 1) s1 += p;
        else if (cb == 2) s2 += p;
        else if (cb == 3) s3 += p;

#pragma unroll
        for (int mk = 1; mk < 8; mk <<= 1) {
            s0 += __shfl_xor_sync(0xffffffffu, s0, mk);
            s1 += __shfl_xor_sync(0xffffffffu, s1, mk);
            s2 += __shfl_xor_sync(0xffffffffu, s2, mk);
            s3 += __shfl_xor_sync(0xffffffffu, s3, mk);
        }

        // gates at cb==0 lanes (4 per warp), one unit each
        if (cb == 0) {
            float ii = sigmoidf_(s0);
            float ff = sigmoidf_(s1);
            float oo = sigmoidf_(s3);
            c = ff * c + ii * tanh_fast(s2);
            float h = oo * tanh_fast(c);
            hsm[b ^ 1][36 * (int)rank + unit] = h;   // self slot = bulk source
            hout[(size_t)t * H_DIM + k_unit] = h;    // off critical path
        }
        __syncthreads();   // self block complete; all hsm[b] reads retired

        // warp 0 lanes 0-7 (minus self): ship 128B self-block to CTA 'lane'
        if (sender) {
            asm volatile("fence.proxy.async.shared::cta;" ::: "memory");
            uint32_t d = b ? dst_b0 : dst_b1;   // step-s output -> buffer b^1
            uint32_t ssrc = b ? src_b0 : src_b1;
            uint32_t m = b ? mdst0 : mdst1;
            bulk_s2cluster(d, ssrc, 128u, m);
        }
    }

    // drain: final sends (step T-1, odd) targeted mb0; complete that phase
    mbar_wait(mb0, par0);
    asm volatile("barrier.cluster.arrive.aligned;" ::: "memory");
    asm volatile("barrier.cluster.wait.aligned;" ::: "memory");
#undef PRE_ISSUE
}

// ---------------- 3) emit: 16 timesteps per block, W_out SMEM-cached -------
__global__ __launch_bounds__(128) void emit_kernel(
    const float* __restrict__ Wout, const float* __restrict__ bout) {
    int t0 = blockIdx.x * 16;
    __shared__ float Wsm[L_TAGS * 512];     // 36 KB
    __shared__ float h[512];
    __shared__ float part[4][18];
    int tid = threadIdx.x;

    for (int i = tid; i < L_TAGS * 512; i += 128) Wsm[i] = Wout[i];

    for (int tl = 0; tl < 16; tl++) {
        int t = t0 + tl;
        __syncthreads();            // also covers Wsm on first iteration
        h[tid]       = g_h[0][(size_t)t * 256 + tid];
        h[tid + 128] = g_h[0][(size_t)t * 256 + 128 + tid];
        h[tid + 256] = g_h[1][(size_t)t * 256 + tid];
        h[tid + 384] = g_h[1][(size_t)t * 256 + 128 + tid];
        __syncthreads();

        if (tid < 72) {
            int jj = tid >> 2, q = tid & 3;
            const float* w = Wsm + jj * 512 + q * 128;
            const float* hh = h + q * 128;
            float a0 = 0.f, a1 = 0.f, a2 = 0.f, a3 = 0.f;
#pragma unroll
            for (int k = 0; k < 128; k += 4) {
                a0 += hh[k] * w[k];
                a1 += hh[k + 1] * w[k + 1];
                a2 += hh[k + 2] * w[k + 2];
                a3 += hh[k + 3] * w[k + 3];
            }
            part[q][jj] = (a0 + a1) + (a2 + a3);
        }
        __syncthreads();
        if (tid < 18)
            g_emit[(size_t)t * L_TAGS + tid] =
                part[0][tid] + part[1][tid] + part[2][tid] + part[3][tid] +
                bout[tid];
    }
}

// ---------------- 4) Viterbi + backtrack (one warp) -------------------------
__global__ void viterbi_kernel(const float* __restrict__ trans,
                               float* __restrict__ out, int write_score) {
    extern __shared__ unsigned char bp[];
    int j = threadIdx.x;
    bool act = (j < L_TAGS);

    float tcol[L_TAGS];
#pragma unroll
    for (int i = 0; i < L_TAGS; i++)
        tcol[i] = act ? trans[i * L_TAGS + j] : 0.f;

    float fv = act ? ((j == START_TAG) ? 0.f : NEGV) : -3.0e38f;
    float e = act ? g_emit[j] : 0.f;

    for (int t = 0; t < T_LEN; t++) {
        float e_next = (act && t + 1 < T_LEN)
                           ? g_emit[(size_t)(t + 1) * L_TAGS + j] : 0.f;
        // precompute all 18 candidate sums (independent, pipelined)
        float sv[L_TAGS];
#pragma unroll
        for (int i = 0; i < L_TAGS; i++)
            sv[i] = __shfl_sync(0xffffffffu, fv, i) + tcol[i];

        // 6 chains of 3 (first-max, strict >), then depth-3 tree merge.
        // Ascending ranges + strict > preserves first-occurrence argmax.
        float bb[6];
        int aa[6];
#pragma unroll
        for (int ch = 0; ch < 6; ch++) {
            float b0 = sv[ch * 3];
            int a0 = ch * 3;
            if (sv[ch * 3 + 1] > b0) { b0 = sv[ch * 3 + 1]; a0 = ch * 3 + 1; }
            if (sv[ch * 3 + 2] > b0) { b0 = sv[ch * 3 + 2]; a0 = ch * 3 + 2; }
            bb[ch] = b0; aa[ch] = a0;
        }
        float m01 = bb[0]; int x01 = aa[0];
        if (bb[1] > m01) { m01 = bb[1]; x01 = aa[1]; }
        float m23 = bb[2]; int x23 = aa[2];
        if (bb[3] > m23) { m23 = bb[3]; x23 = aa[3]; }
        float m45 = bb[4]; int x45 = aa[4];
        if (bb[5] > m45) { m45 = bb[5]; x45 = aa[5]; }
        float m03 = m01; int x03 = x01;
        if (m23 > m03) { m03 = m23; x03 = x23; }
        float best = m03; int arg = x03;
        if (m45 > best) { best = m45; arg = x45; }

        if (act) {
            bp[t * L_TAGS + j] = (unsigned char)arg;
            fv = best + e;
        }
        e = e_next;
    }

    float term = act ? (fv + trans[j * L_TAGS + STOP_TAG]) : -3.4e38f;
    int ai = j;
#pragma unroll
    for (int off = 16; off > 0; off >>= 1) {
        float ov = __shfl_xor_sync(0xffffffffu, term, off);
        int oi = __shfl_xor_sync(0xffffffffu, ai, off);
        if (ov > term || (ov == term && oi < ai)) { term = ov; ai = oi; }
    }

    if (j == 0) {
        if (write_score) out[0] = term;
        float* path = out + write_score;
        int tag = ai;
        for (int t = T_LEN - 1; t >= 0; t--) {
            path[t] = (float)tag;
            tag = bp[t * L_TAGS + tag];
        }
    }
}

// ---------------- launch ----------------------------------------------------
extern "C" void kernel_launch(void* const* d_in, const int* in_sizes, int n_in,
                              void* d_out, int out_size) {
    const int*   feats  = (const int*)d_in[0];
    const float* emb    = (const float*)d_in[1];
    const float* w_ih_f = (const float*)d_in[2];
    const float* w_hh_f = (const float*)d_in[3];
    const float* b_f    = (const float*)d_in[4];
    const float* w_ih_b = (const float*)d_in[5];
    const float* w_hh_b = (const float*)d_in[6];
    const float* b_b    = (const float*)d_in[7];
    const float* W_out  = (const float*)d_in[8];
    const float* b_out  = (const float*)d_in[9];
    const float* trans  = (const float*)d_in[10];

    dim3 gg(G_DIM / 64, T_LEN / 64, 2);
    gemm_pre_kernel<<<gg, 256>>>(feats, emb, w_ih_f, w_ih_b, b_f, b_b);

    lstm_cluster_kernel<<<16, 256>>>(w_hh_f, w_hh_b);

    emit_kernel<<<T_LEN / 16, 128>>>(W_out, b_out);

    int ws = (out_size > T_LEN) ? 1 : 0;   // layout: [path_score, path...]
    static int smem_set = 0;
    if (!smem_set) {
        cudaFuncSetAttribute(viterbi_kernel,
                             cudaFuncAttributeMaxDynamicSharedMemorySize,
                             T_LEN * L_TAGS + 1024);
        smem_set = 1;
    }
    viterbi_kernel<<<1, 32, T_LEN * L_TAGS>>>(trans, (float*)d_out, ws);
}

// round 14
// speedup vs baseline: 1.3489x; 1.0321x over previous
#include <cuda_runtime.h>
#include <cstdint>

#define T_LEN 4096
#define E_DIM 256
#define H_DIM 256
#define G_DIM 1024   // 4*H
#define L_TAGS 18
#define START_TAG 16
#define STOP_TAG 17
#define NEGV (-10000.0f)

// ---------------- device scratch (static: no allocations allowed) ----------
__device__ float g_pre[2][(size_t)T_LEN * G_DIM];   // pre-activations, fwd/bwd
__device__ float g_h[2][(size_t)T_LEN * H_DIM];     // hf / hb
__device__ float g_emit[(size_t)T_LEN * L_TAGS];    // emissions
// idempotent tile-ready flags: bit nt set when (dir, mtile) n-subtile done.
// Monotone across graph replays; pre rewrites are byte-identical -> benign.
__device__ unsigned g_tile_flag[2][64];

// ---------------- small helpers -------------------------------------------
__device__ __forceinline__ unsigned long long ffma2(unsigned long long a,
                                                    unsigned long long b,
                                                    unsigned long long c) {
    unsigned long long d;
    asm("fma.rn.f32x2 %0, %1, %2, %3;" : "=l"(d) : "l"(a), "l"(b), "l"(c));
    return d;
}
__device__ __forceinline__ float2 unpackf2(unsigned long long v) {
    float2 r;
    asm("mov.b64 {%0, %1}, %2;" : "=f"(r.x), "=f"(r.y) : "l"(v));
    return r;
}
__device__ __forceinline__ float sigmoidf_(float x) {
    return __fdividef(1.0f, 1.0f + __expf(-x));
}
__device__ __forceinline__ float tanh_fast(float x) {
    float e = __expf(2.0f * x);
    return 1.0f - __fdividef(2.0f, e + 1.0f);
}
__device__ __forceinline__ uint32_t smem_u32(const void* p) {
    uint32_t a;
    asm("{ .reg .u64 t; cvta.to.shared.u64 t, %1; cvt.u32.u64 %0, t; }"
        : "=r"(a) : "l"(p));
    return a;
}
__device__ __forceinline__ uint32_t mapa_u32(uint32_t local, uint32_t rank) {
    uint32_t r;
    asm("mapa.shared::cluster.u32 %0, %1, %2;" : "=r"(r) : "r"(local), "r"(rank));
    return r;
}
__device__ __forceinline__ void mbar_init(uint32_t mbar, uint32_t count) {
    asm volatile("mbarrier.init.shared::cta.b64 [%0], %1;" :: "r"(mbar), "r"(count)
                 : "memory");
}
__device__ __forceinline__ void mbar_expect_tx(uint32_t mbar, uint32_t bytes) {
    asm volatile("mbarrier.arrive.expect_tx.shared::cta.b64 _, [%0], %1;"
                 :: "r"(mbar), "r"(bytes) : "memory");
}
// spin-then-sleep wait: one fast-path try_wait, then HW-sleep hinted loop.
__device__ __forceinline__ void mbar_wait(uint32_t mbar, uint32_t parity) {
    uint32_t done;
    asm volatile(
        "{\n\t.reg .pred P;\n\t"
        "mbarrier.try_wait.parity.acquire.cta.shared::cta.b64 P, [%1], %2;\n\t"
        "selp.b32 %0, 1, 0, P;\n\t}"
        : "=r"(done) : "r"(mbar), "r"(parity) : "memory");
    if (!done) {
        asm volatile(
            "{\n\t.reg .pred P;\n\t"
            "W_%=:\n\t"
            "mbarrier.try_wait.parity.acquire.cta.shared::cta.b64 P, [%0], %1, 0x989680;\n\t"
            "@P bra.uni D_%=;\n\t"
            "bra.uni W_%=;\n\t"
            "D_%=:\n\t}"
            :: "r"(mbar), "r"(parity) : "memory");
    }
}
// one-shot 128B SMEM -> remote-CTA SMEM with single tx update on remote mbar
__device__ __forceinline__ void bulk_s2cluster(uint32_t dst, uint32_t src,
                                               uint32_t bytes, uint32_t rmbar) {
    asm volatile(
        "cp.async.bulk.shared::cluster.shared::cta.mbarrier::complete_tx::bytes "
        "[%0], [%1], %2, [%3];"
        :: "r"(dst), "r"(src), "r"(bytes), "r"(rmbar) : "memory");
}
__device__ __forceinline__ void cp_async16(uint32_t dst, const void* src) {
    asm volatile("cp.async.ca.shared.global [%0], [%1], 16;"
                 :: "r"(dst), "l"(src) : "memory");
}
__device__ __forceinline__ unsigned ld_acq_gpu(const unsigned* p) {
    unsigned v;
    asm volatile("ld.acquire.gpu.global.b32 %0, [%1];" : "=r"(v) : "l"(p)
                 : "memory");
    return v;
}

// ---------------- SMEM union for the fused kernel ---------------------------
struct LstmSmem {
    float hsm[2][288];          // 36-stride padded h, double-buffered
    float pre_s[3][16][144];    // ring-3: 16 steps x 4x36
    float hstage[2][32];        // fresh h, double-buffered
    unsigned long long mbar[2];
};
struct GemmSmem {
    float As[64][68];
    float Bs[64][68];
    int fid[64];
};
#define SMEM_RAW_BYTES (sizeof(GemmSmem) > sizeof(LstmSmem) ? \
                        sizeof(GemmSmem) : sizeof(LstmSmem))

// ---------------- worker: one 64x64 gemm tile --------------------------------
__device__ void gemm_tile(GemmSmem* S, int dir, int m0, int n0,
                          const int* __restrict__ feats,
                          const float* __restrict__ emb,
                          const float* __restrict__ wih,
                          const float* __restrict__ bias) {
    float* out = g_pre[dir];
    int tid = threadIdx.x;
    int tx = tid & 15, ty = tid >> 4;

    if (tid < 64) S->fid[tid] = feats[m0 + tid];
    __syncthreads();

    float acc[4][4];
#pragma unroll
    for (int i = 0; i < 4; i++)
#pragma unroll
        for (int j = 0; j < 4; j++) acc[i][j] = 0.f;

    for (int kb = 0; kb < 4; kb++) {
#pragma unroll
        for (int i = 0; i < 16; i++) {
            int idx = tid + i * 256;
            int m = idx >> 6, k = idx & 63;
            S->As[k][m] = emb[(size_t)S->fid[m] * E_DIM + kb * 64 + k];
            S->Bs[k][m] = wih[(size_t)(n0 + m) * E_DIM + kb * 64 + k];
        }
        __syncthreads();
#pragma unroll
        for (int k = 0; k < 64; k++) {
            float4 a4 = *(const float4*)&S->As[k][ty * 4];
            float4 b4 = *(const float4*)&S->Bs[k][tx * 4];
            float av[4] = {a4.x, a4.y, a4.z, a4.w};
            float bv[4] = {b4.x, b4.y, b4.z, b4.w};
#pragma unroll
            for (int i = 0; i < 4; i++)
#pragma unroll
                for (int j = 0; j < 4; j++) acc[i][j] += av[i] * bv[j];
        }
        __syncthreads();
    }
#pragma unroll
    for (int j = 0; j < 4; j++) {
        float bj = bias[n0 + tx * 4 + j];
#pragma unroll
        for (int i = 0; i < 4; i++)
            out[(size_t)(m0 + ty * 4 + i) * G_DIM + n0 + tx * 4 + j] =
                acc[i][j] + bj;
    }
}

// ---------------- fused kernel: clusters 0-1 = LSTM, 2-15 = gemm workers ----
__global__ void __cluster_dims__(8, 1, 1) __launch_bounds__(256, 1)
fused_kernel(const int* __restrict__ feats, const float* __restrict__ emb,
             const float* __restrict__ wih_f, const float* __restrict__ wih_b,
             const float* __restrict__ b_f, const float* __restrict__ b_b,
             const float* __restrict__ whh_f, const float* __restrict__ whh_b) {
    __shared__ __align__(16) char smem_raw[SMEM_RAW_BYTES];
    int cid = blockIdx.x >> 3;
    int tid = threadIdx.x;

    // ================= WORKER path: input GEMM tiles =================
    if (cid >= 2) {
        GemmSmem* S = (GemmSmem*)smem_raw;
        int w = blockIdx.x - 16;                   // 0..111
        for (int k = w; k < 2048; k += 112) {
            int dir = k & 1;
            int half = k >> 1;                     // 0..1023
            int mt = half >> 4;                    // 0..63
            int nt = half & 15;                    // 0..15
            int mtile = dir ? (63 - mt) : mt;      // bwd produced descending
            gemm_tile(S, dir, mtile * 64, nt * 64, feats, emb,
                      dir ? wih_b : wih_f, dir ? b_b : b_f);
            __threadfence();
            __syncthreads();
            if (tid == 0)
                atomicOr(&g_tile_flag[dir][mtile], 1u << nt);
        }
        return;
    }

    // ================= LSTM path (R9 body + tile polls) =================
    LstmSmem* S = (LstmSmem*)smem_raw;
    uint32_t rank;
    asm("mov.u32 %0, %%cluster_ctarank;" : "=r"(rank));
    int dir = cid;

    const float* whh = dir ? whh_b : whh_f;
    const float* pre = g_pre[dir];
    float* hout = g_h[dir];

    int lane = tid & 31, warp = tid >> 5;       // 8 warps
    int cb = lane & 7;                          // column block [32cb,32cb+32)
    int ub = lane >> 3;                         // unit within warp (0..3)
    int unit = warp * 4 + ub;                   // local unit 0..31
    int k_unit = (int)rank * 32 + unit;         // global hidden unit

    // weights: all 4 gates of this unit, 32 cols -> 128 floats = 64 f32x2
    unsigned long long wr[4][16];
#pragma unroll
    for (int gg = 0; gg < 4; gg++) {
        const ulonglong2* wp = (const ulonglong2*)(
            whh + (size_t)(gg * 256 + k_unit) * H_DIM + cb * 32);
#pragma unroll
        for (int q = 0; q < 8; q++) {
            ulonglong2 v = wp[q];
            wr[gg][2 * q] = v.x;
            wr[gg][2 * q + 1] = v.y;
        }
    }

    for (int i = tid; i < 288; i += 256) {
        S->hsm[0][i] = 0.f;
        S->hsm[1][i] = 0.f;
    }

    uint32_t hbase = smem_u32(&S->hsm[0][0]);
    uint32_t pbase = smem_u32(&S->pre_s[0][0][0]);
    uint32_t sbase = smem_u32(&S->hstage[0][0]);
    uint32_t mb0 = smem_u32(&S->mbar[0]);
    uint32_t mb1 = smem_u32(&S->mbar[1]);

    if (tid == 0) {
        mbar_init(mb0, 1);
        mbar_init(mb1, 1);
        mbar_expect_tx(mb1, 896);    // step-0 sends (7 peers) land on mb1
    }

    int last_tile = -1;   // tid0-tracked confirmed tile

#define TILE_OF(ck) (dir ? ((4080 - 16 * (ck)) >> 6) : ((ck) >> 2))
#define POLL_TILE(ck)                                                         \
    do {                                                                      \
        int tile_ = TILE_OF(ck);                                              \
        if (tid == 0 && tile_ != last_tile) {                                 \
            while (ld_acq_gpu(&g_tile_flag[dir][tile_]) != 0xFFFFu)           \
                __nanosleep(200);                                             \
            last_tile = tile_;                                                \
        }                                                                     \
        __syncthreads();                                                      \
    } while (0)

#define PRE_ISSUE(ck, ring)                                                   \
    do {                                                                      \
        _Pragma("unroll")                                                     \
        for (int pp = 0; pp < 2; pp++) {                                      \
            int idx = tid + pp * 256;                                         \
            int si_ = idx >> 5;                                               \
            int ga_ = (idx & 31) >> 3, l8_ = idx & 7;                         \
            int ss_ = (ck) * 16 + si_;                                        \
            int tt_ = dir ? (T_LEN - 1 - ss_) : ss_;                          \
            const float* src_ = pre + (size_t)tt_ * G_DIM + ga_ * 256 +       \
                                (int)rank * 32 + l8_ * 4;                     \
            uint32_t dst_ = pbase +                                           \
                (uint32_t)(((ring) * 16 + si_) * 144 + ga_ * 36 + l8_ * 4) * 4u; \
            cp_async16(dst_, src_);                                           \
        }                                                                     \
        asm volatile("cp.async.commit_group;" ::: "memory");                  \
    } while (0)

    POLL_TILE(0);
    PRE_ISSUE(0, 0);
    POLL_TILE(1);
    PRE_ISSUE(1, 1);

    // sender setup (warp 0 lanes 0-7, skipping self): this CTA's 32 h =
    // 128B contiguous at float-offset 36*rank in every CTA's hsm buffer.
    uint32_t dst_b0 = 0, dst_b1 = 0, mdst0 = 0, mdst1 = 0;
    bool sender = (warp == 0 && lane < 8 && (uint32_t)lane != rank);
    if (warp == 0 && lane < 8) {
        dst_b0 = mapa_u32(hbase + (uint32_t)(36 * rank) * 4u, (uint32_t)lane);
        dst_b1 = mapa_u32(hbase + (uint32_t)(288 + 36 * rank) * 4u,
                          (uint32_t)lane);
        mdst0 = mapa_u32(mb0, (uint32_t)lane);
        mdst1 = mapa_u32(mb1, (uint32_t)lane);
    }

    __syncthreads();
    asm volatile("barrier.cluster.arrive.aligned;" ::: "memory");
    asm volatile("barrier.cluster.wait.aligned;" ::: "memory");

    float c = 0.f;                 // cell state at cb==0 lanes
    uint32_t par0 = 0, par1 = 0;

    for (int s = 0; s < T_LEN; s++) {
        int b = s & 1;
        int si = s & 15;
        int t = dir ? (T_LEN - 1 - s) : s;

        if (si == 0) {
            int c2 = (s >> 4) + 2;
            if (c2 < (T_LEN / 16)) {
                POLL_TILE(c2);
                PRE_ISSUE(c2, c2 % 3);
                asm volatile("cp.async.wait_group 2;" ::: "memory");
            } else {
                asm volatile("cp.async.wait_group 0;" ::: "memory");
            }
            __syncthreads();
        }
        int buf = (s >> 4) % 3;

        // pre for gate cb of this unit (only cb<4 lanes add it)
        float p = (cb < 4) ? S->pre_s[buf][si][cb * 36 + unit] : 0.f;

        // wait until all 7 remote CTAs delivered h for this step
        if (s > 0) {
            if (b) { mbar_wait(mb1, par1); par1 ^= 1; }
            else   { mbar_wait(mb0, par0); par0 ^= 1; }
        }
        if (tid == 0) mbar_expect_tx(b ? mb1 : mb0, 896);

        // matvec: 4 gate rows x 32 cols; h from hsm[b] block cb
        const ulonglong2* h2 = (const ulonglong2*)(&S->hsm[b][cb * 36]);
        unsigned long long a0 = 0ull, a1 = 0ull, a2 = 0ull, a3 = 0ull;
#pragma unroll
        for (int q = 0; q < 8; q++) {
            ulonglong2 hv = h2[q];
            a0 = ffma2(wr[0][2 * q], hv.x, a0);
            a1 = ffma2(wr[1][2 * q], hv.x, a1);
            a2 = ffma2(wr[2][2 * q], hv.x, a2);
            a3 = ffma2(wr[3][2 * q], hv.x, a3);
            a0 = ffma2(wr[0][2 * q + 1], hv.y, a0);
            a1 = ffma2(wr[1][2 * q + 1], hv.y, a1);
            a2 = ffma2(wr[2][2 * q + 1], hv.y, a2);
            a3 = ffma2(wr[3][2 * q + 1], hv.y, a3);
        }
        float2 f0 = unpackf2(a0), f1 = unpackf2(a1);
        float2 f2 = unpackf2(a2), f3 = unpackf2(a3);
        float s0 = f0.x + f0.y, s1 = f1.x + f1.y;
        float s2 = f2.x + f2.y, s3 = f3.x + f3.y;

        if (cb == 0) s0 += p;
        else if (cb == 1) s1 += p;
        else if (cb == 2) s2 += p;
        else if (cb == 3) s3 += p;

#pragma unroll
        for (int mk = 1; mk < 8; mk <<= 1) {
            s0 += __shfl_xor_sync(0xffffffffu, s0, mk);
            s1 += __shfl_xor_sync(0xffffffffu, s1, mk);
            s2 += __shfl_xor_sync(0xffffffffu, s2, mk);
            s3 += __shfl_xor_sync(0xffffffffu, s3, mk);
        }

        // gates at cb==0 lanes (4 per warp), one unit each
        if (cb == 0) {
            float ii = sigmoidf_(s0);
            float ff = sigmoidf_(s1);
            float oo = sigmoidf_(s3);
            c = ff * c + ii * tanh_fast(s2);
            float h = oo * tanh_fast(c);
            S->hstage[b ^ 1][unit] = h;
            S->hsm[b ^ 1][36 * (int)rank + unit] = h;   // self-delivery
            hout[(size_t)t * H_DIM + k_unit] = h;       // off critical path
        }
        __syncthreads();   // hstage + local hsm staged; hsm[b] reads retired

        // warp 0 lanes 0-7 (minus self): ship 128B block to CTA 'lane'
        if (sender) {
            asm volatile("fence.proxy.async.shared::cta;" ::: "memory");
            uint32_t d = b ? dst_b0 : dst_b1;   // step-s output -> buffer b^1
            uint32_t m = b ? mdst0 : mdst1;
            bulk_s2cluster(d, sbase + (uint32_t)((b ^ 1) * 32) * 4u, 128u, m);
        }
    }

    // drain: final sends (step T-1, odd) targeted mb0; complete that phase
    mbar_wait(mb0, par0);
    asm volatile("barrier.cluster.arrive.aligned;" ::: "memory");
    asm volatile("barrier.cluster.wait.aligned;" ::: "memory");
#undef PRE_ISSUE
#undef POLL_TILE
#undef TILE_OF
}

// ---------------- 3) emit: 16 timesteps per block, W_out SMEM-cached -------
__global__ __launch_bounds__(128) void emit_kernel(
    const float* __restrict__ Wout, const float* __restrict__ bout) {
    int t0 = blockIdx.x * 16;
    __shared__ float Wsm[L_TAGS * 512];     // 36 KB
    __shared__ float h[512];
    __shared__ float part[4][18];
    int tid = threadIdx.x;

    for (int i = tid; i < L_TAGS * 512; i += 128) Wsm[i] = Wout[i];

    for (int tl = 0; tl < 16; tl++) {
        int t = t0 + tl;
        __syncthreads();            // also covers Wsm on first iteration
        h[tid]       = g_h[0][(size_t)t * 256 + tid];
        h[tid + 128] = g_h[0][(size_t)t * 256 + 128 + tid];
        h[tid + 256] = g_h[1][(size_t)t * 256 + tid];
        h[tid + 384] = g_h[1][(size_t)t * 256 + 128 + tid];
        __syncthreads();

        if (tid < 72) {
            int jj = tid >> 2, q = tid & 3;
            const float* w = Wsm + jj * 512 + q * 128;
            const float* hh = h + q * 128;
            float a0 = 0.f, a1 = 0.f, a2 = 0.f, a3 = 0.f;
#pragma unroll
            for (int k = 0; k < 128; k += 4) {
                a0 += hh[k] * w[k];
                a1 += hh[k + 1] * w[k + 1];
                a2 += hh[k + 2] * w[k + 2];
                a3 += hh[k + 3] * w[k + 3];
            }
            part[q][jj] = (a0 + a1) + (a2 + a3);
        }
        __syncthreads();
        if (tid < 18)
            g_emit[(size_t)t * L_TAGS + tid] =
                part[0][tid] + part[1][tid] + part[2][tid] + part[3][tid] +
                bout[tid];
    }
}

// ---------------- 4) Viterbi + backtrack (one warp, tree merge) -------------
__global__ void viterbi_kernel(const float* __restrict__ trans,
                               float* __restrict__ out, int write_score) {
    extern __shared__ unsigned char bp[];
    int j = threadIdx.x;
    bool act = (j < L_TAGS);

    float tcol[L_TAGS];
#pragma unroll
    for (int i = 0; i < L_TAGS; i++)
        tcol[i] = act ? trans[i * L_TAGS + j] : 0.f;

    float fv = act ? ((j == START_TAG) ? 0.f : NEGV) : -3.0e38f;
    float e = act ? g_emit[j] : 0.f;

    for (int t = 0; t < T_LEN; t++) {
        float e_next = (act && t + 1 < T_LEN)
                           ? g_emit[(size_t)(t + 1) * L_TAGS + j] : 0.f;
        float sv[L_TAGS];
#pragma unroll
        for (int i = 0; i < L_TAGS; i++)
            sv[i] = __shfl_sync(0xffffffffu, fv, i) + tcol[i];

        // 6 chains of 3 (first-max, strict >), then depth-3 tree merge.
        // Ascending ranges + strict > preserves first-occurrence argmax.
        float bb[6];
        int aa[6];
#pragma unroll
        for (int ch = 0; ch < 6; ch++) {
            float b0 = sv[ch * 3];
            int a0 = ch * 3;
            if (sv[ch * 3 + 1] > b0) { b0 = sv[ch * 3 + 1]; a0 = ch * 3 + 1; }
            if (sv[ch * 3 + 2] > b0) { b0 = sv[ch * 3 + 2]; a0 = ch * 3 + 2; }
            bb[ch] = b0; aa[ch] = a0;
        }
        float m01 = bb[0]; int x01 = aa[0];
        if (bb[1] > m01) { m01 = bb[1]; x01 = aa[1]; }
        float m23 = bb[2]; int x23 = aa[2];
        if (bb[3] > m23) { m23 = bb[3]; x23 = aa[3]; }
        float m45 = bb[4]; int x45 = aa[4];
        if (bb[5] > m45) { m45 = bb[5]; x45 = aa[5]; }
        float m03 = m01; int x03 = x01;
        if (m23 > m03) { m03 = m23; x03 = x23; }
        float best = m03; int arg = x03;
        if (m45 > best) { best = m45; arg = x45; }

        if (act) {
            bp[t * L_TAGS + j] = (unsigned char)arg;
            fv = best + e;
        }
        e = e_next;
    }

    float term = act ? (fv + trans[j * L_TAGS + STOP_TAG]) : -3.4e38f;
    int ai = j;
#pragma unroll
    for (int off = 16; off > 0; off >>= 1) {
        float ov = __shfl_xor_sync(0xffffffffu, term, off);
        int oi = __shfl_xor_sync(0xffffffffu, ai, off);
        if (ov > term || (ov == term && oi < ai)) { term = ov; ai = oi; }
    }

    if (j == 0) {
        if (write_score) out[0] = term;
        float* path = out + write_score;
        int tag = ai;
        for (int t = T_LEN - 1; t >= 0; t--) {
            path[t] = (float)tag;
            tag = bp[t * L_TAGS + tag];
        }
    }
}

// ---------------- launch ----------------------------------------------------
extern "C" void kernel_launch(void* const* d_in, const int* in_sizes, int n_in,
                              void* d_out, int out_size) {
    const int*   feats  = (const int*)d_in[0];
    const float* emb    = (const float*)d_in[1];
    const float* w_ih_f = (const float*)d_in[2];
    const float* w_hh_f = (const float*)d_in[3];
    const float* b_f    = (const float*)d_in[4];
    const float* w_ih_b = (const float*)d_in[5];
    const float* w_hh_b = (const float*)d_in[6];
    const float* b_b    = (const float*)d_in[7];
    const float* W_out  = (const float*)d_in[8];
    const float* b_out  = (const float*)d_in[9];
    const float* trans  = (const float*)d_in[10];

    // fused: 16 clusters of 8 CTAs; clusters 0-1 = LSTM fwd/bwd,
    // clusters 2-15 = 112 gemm worker CTAs running concurrently.
    fused_kernel<<<128, 256>>>(feats, emb, w_ih_f, w_ih_b, b_f, b_b,
                               w_hh_f, w_hh_b);

    emit_kernel<<<T_LEN / 16, 128>>>(W_out, b_out);

    int ws = (out_size > T_LEN) ? 1 : 0;   // layout: [path_score, path...]
    static int smem_set = 0;
    if (!smem_set) {
        cudaFuncSetAttribute(viterbi_kernel,
                             cudaFuncAttributeMaxDynamicSharedMemorySize,
                             T_LEN * L_TAGS + 1024);
        smem_set = 1;
    }
    viterbi_kernel<<<1, 32, T_LEN * L_TAGS>>>(trans, (float*)d_out, ws);
}

// round 15
// speedup vs baseline: 1.3618x; 1.0095x over previous
#include <cuda_runtime.h>
#include <cstdint>

#define T_LEN 4096
#define E_DIM 256
#define H_DIM 256
#define G_DIM 1024   // 4*H
#define L_TAGS 18
#define START_TAG 16
#define STOP_TAG 17
#define NEGV (-10000.0f)

// ---------------- device scratch (static: no allocations allowed) ----------
__device__ float g_pre[2][(size_t)T_LEN * G_DIM];   // pre-activations, fwd/bwd
__device__ float g_h[2][(size_t)T_LEN * H_DIM];     // hf / hb
__device__ float g_emit[(size_t)T_LEN * L_TAGS];    // emissions

// ---------------- small helpers -------------------------------------------
__device__ __forceinline__ unsigned long long ffma2(unsigned long long a,
                                                    unsigned long long b,
                                                    unsigned long long c) {
    unsigned long long d;
    asm("fma.rn.f32x2 %0, %1, %2, %3;" : "=l"(d) : "l"(a), "l"(b), "l"(c));
    return d;
}
__device__ __forceinline__ float2 unpackf2(unsigned long long v) {
    float2 r;
    asm("mov.b64 {%0, %1}, %2;" : "=f"(r.x), "=f"(r.y) : "l"(v));
    return r;
}
__device__ __forceinline__ float sigmoidf_(float x) {
    return __fdividef(1.0f, 1.0f + __expf(-x));
}
__device__ __forceinline__ float tanh_fast(float x) {
    float e = __expf(2.0f * x);
    return 1.0f - __fdividef(2.0f, e + 1.0f);
}
__device__ __forceinline__ uint32_t smem_u32(const void* p) {
    uint32_t a;
    asm("{ .reg .u64 t; cvta.to.shared.u64 t, %1; cvt.u32.u64 %0, t; }"
        : "=r"(a) : "l"(p));
    return a;
}
__device__ __forceinline__ uint32_t mapa_u32(uint32_t local, uint32_t rank) {
    uint32_t r;
    asm("mapa.shared::cluster.u32 %0, %1, %2;" : "=r"(r) : "r"(local), "r"(rank));
    return r;
}
__device__ __forceinline__ void mbar_init(uint32_t mbar, uint32_t count) {
    asm volatile("mbarrier.init.shared::cta.b64 [%0], %1;" :: "r"(mbar), "r"(count)
                 : "memory");
}
__device__ __forceinline__ void mbar_expect_tx(uint32_t mbar, uint32_t bytes) {
    asm volatile("mbarrier.arrive.expect_tx.shared::cta.b64 _, [%0], %1;"
                 :: "r"(mbar), "r"(bytes) : "memory");
}
// spin-then-sleep wait: one fast-path try_wait, then HW-sleep hinted loop.
__device__ __forceinline__ void mbar_wait(uint32_t mbar, uint32_t parity) {
    uint32_t done;
    asm volatile(
        "{\n\t.reg .pred P;\n\t"
        "mbarrier.try_wait.parity.acquire.cta.shared::cta.b64 P, [%1], %2;\n\t"
        "selp.b32 %0, 1, 0, P;\n\t}"
        : "=r"(done) : "r"(mbar), "r"(parity) : "memory");
    if (!done) {
        asm volatile(
            "{\n\t.reg .pred P;\n\t"
            "W_%=:\n\t"
            "mbarrier.try_wait.parity.acquire.cta.shared::cta.b64 P, [%0], %1, 0x989680;\n\t"
            "@P bra.uni D_%=;\n\t"
            "bra.uni W_%=;\n\t"
            "D_%=:\n\t}"
            :: "r"(mbar), "r"(parity) : "memory");
    }
}
// one-shot 128B SMEM -> remote-CTA SMEM with single tx update on remote mbar
__device__ __forceinline__ void bulk_s2cluster(uint32_t dst, uint32_t src,
                                               uint32_t bytes, uint32_t rmbar) {
    asm volatile(
        "cp.async.bulk.shared::cluster.shared::cta.mbarrier::complete_tx::bytes "
        "[%0], [%1], %2, [%3];"
        :: "r"(dst), "r"(src), "r"(bytes), "r"(rmbar) : "memory");
}
__device__ __forceinline__ void cp_async16(uint32_t dst, const void* src) {
    asm volatile("cp.async.ca.shared.global [%0], [%1], 16;"
                 :: "r"(dst), "l"(src) : "memory");
}

// ---------------- 1) fused gather + input GEMM -----------------------------
__global__ __launch_bounds__(256) void gemm_pre_kernel(
    const int* __restrict__ feats, const float* __restrict__ emb,
    const float* __restrict__ wih_f, const float* __restrict__ wih_b,
    const float* __restrict__ b_f, const float* __restrict__ b_b) {
    int dir = blockIdx.z;
    const float* wih  = dir ? wih_b : wih_f;
    const float* bias = dir ? b_b : b_f;
    float* out = g_pre[dir];

    int m0 = blockIdx.y * 64;
    int n0 = blockIdx.x * 64;

    __shared__ __align__(16) float As[64][68];
    __shared__ __align__(16) float Bs[64][68];
    __shared__ int fid[64];

    int tid = threadIdx.x;
    int tx = tid & 15, ty = tid >> 4;

    if (tid < 64) fid[tid] = feats[m0 + tid];
    __syncthreads();

    float acc[4][4];
#pragma unroll
    for (int i = 0; i < 4; i++)
#pragma unroll
        for (int j = 0; j < 4; j++) acc[i][j] = 0.f;

    for (int kb = 0; kb < 4; kb++) {
#pragma unroll
        for (int i = 0; i < 16; i++) {
            int idx = tid + i * 256;
            int m = idx >> 6, k = idx & 63;
            As[k][m] = emb[(size_t)fid[m] * E_DIM + kb * 64 + k];
            Bs[k][m] = wih[(size_t)(n0 + m) * E_DIM + kb * 64 + k];
        }
        __syncthreads();
#pragma unroll
        for (int k = 0; k < 64; k++) {
            float4 a4 = *(const float4*)&As[k][ty * 4];
            float4 b4 = *(const float4*)&Bs[k][tx * 4];
            float av[4] = {a4.x, a4.y, a4.z, a4.w};
            float bv[4] = {b4.x, b4.y, b4.z, b4.w};
#pragma unroll
            for (int i = 0; i < 4; i++)
#pragma unroll
                for (int j = 0; j < 4; j++) acc[i][j] += av[i] * bv[j];
        }
        __syncthreads();
    }
#pragma unroll
    for (int j = 0; j < 4; j++) {
        float bj = bias[n0 + tx * 4 + j];
#pragma unroll
        for (int i = 0; i < 4; i++)
            out[(size_t)(m0 + ty * 4 + i) * G_DIM + n0 + tx * 4 + j] =
                acc[i][j] + bj;
    }
}

// ---------------- 2) LSTM recurrence: R9 exactly (validated optimum) -------
__global__ void __cluster_dims__(8, 1, 1) __launch_bounds__(256, 1)
lstm_cluster_kernel(const float* __restrict__ whh_f,
                    const float* __restrict__ whh_b) {
    __shared__ __align__(16) float hsm[2][288];        // 36-stride padded h
    __shared__ __align__(16) float pre_s[3][16][144];  // 16 steps x 4x36
    __shared__ __align__(16) float hstage[2][32];      // fresh h, dbl-buffered
    __shared__ __align__(8) unsigned long long mbar_sm[2];

    uint32_t rank;
    asm("mov.u32 %0, %%cluster_ctarank;" : "=r"(rank));
    int dir = blockIdx.x >> 3;

    const float* whh = dir ? whh_b : whh_f;
    const float* pre = g_pre[dir];
    float* hout = g_h[dir];

    int tid = threadIdx.x;
    int lane = tid & 31, warp = tid >> 5;       // 8 warps
    int cb = lane & 7;                          // column block [32cb,32cb+32)
    int ub = lane >> 3;                         // unit within warp (0..3)
    int unit = warp * 4 + ub;                   // local unit 0..31
    int k_unit = (int)rank * 32 + unit;         // global hidden unit

    // weights: all 4 gates of this unit, 32 cols -> 128 floats = 64 f32x2
    unsigned long long wr[4][16];
#pragma unroll
    for (int gg = 0; gg < 4; gg++) {
        const ulonglong2* wp = (const ulonglong2*)(
            whh + (size_t)(gg * 256 + k_unit) * H_DIM + cb * 32);
#pragma unroll
        for (int q = 0; q < 8; q++) {
            ulonglong2 v = wp[q];
            wr[gg][2 * q] = v.x;
            wr[gg][2 * q + 1] = v.y;
        }
    }

    for (int i = tid; i < 288; i += 256) { hsm[0][i] = 0.f; hsm[1][i] = 0.f; }

    uint32_t hbase = smem_u32(&hsm[0][0]);
    uint32_t pbase = smem_u32(&pre_s[0][0][0]);
    uint32_t sbase = smem_u32(&hstage[0][0]);
    uint32_t mb0 = smem_u32(&mbar_sm[0]);
    uint32_t mb1 = smem_u32(&mbar_sm[1]);

    if (tid == 0) {
        mbar_init(mb0, 1);
        mbar_init(mb1, 1);
        mbar_expect_tx(mb1, 896);    // step-0 sends (7 peers) land on mb1
    }

#define PRE_ISSUE(ck, ring)                                                   \
    do {                                                                      \
        _Pragma("unroll")                                                     \
        for (int pp = 0; pp < 2; pp++) {                                      \
            int idx = tid + pp * 256;                                         \
            int si_ = idx >> 5;                                               \
            int ga_ = (idx & 31) >> 3, l8_ = idx & 7;                         \
            int ss_ = (ck) * 16 + si_;                                        \
            int tt_ = dir ? (T_LEN - 1 - ss_) : ss_;                          \
            const float* src_ = pre + (size_t)tt_ * G_DIM + ga_ * 256 +       \
                                (int)rank * 32 + l8_ * 4;                     \
            uint32_t dst_ = pbase +                                           \
                (uint32_t)(((ring) * 16 + si_) * 144 + ga_ * 36 + l8_ * 4) * 4u; \
            cp_async16(dst_, src_);                                           \
        }                                                                     \
        asm volatile("cp.async.commit_group;" ::: "memory");                  \
    } while (0)

    PRE_ISSUE(0, 0);
    PRE_ISSUE(1, 1);

    // sender setup (warp 0 lanes 0-7, skipping self): this CTA's 32 h =
    // 128B contiguous at float-offset 36*rank in every CTA's hsm buffer.
    uint32_t dst_b0 = 0, dst_b1 = 0, mdst0 = 0, mdst1 = 0;
    bool sender = (warp == 0 && lane < 8 && (uint32_t)lane != rank);
    if (warp == 0 && lane < 8) {
        dst_b0 = mapa_u32(hbase + (uint32_t)(36 * rank) * 4u, (uint32_t)lane);
        dst_b1 = mapa_u32(hbase + (uint32_t)(288 + 36 * rank) * 4u, (uint32_t)lane);
        mdst0 = mapa_u32(mb0, (uint32_t)lane);
        mdst1 = mapa_u32(mb1, (uint32_t)lane);
    }

    __syncthreads();
    asm volatile("barrier.cluster.arrive.aligned;" ::: "memory");
    asm volatile("barrier.cluster.wait.aligned;" ::: "memory");

    float c = 0.f;                 // cell state at cb==0 lanes
    uint32_t par0 = 0, par1 = 0;

    for (int s = 0; s < T_LEN; s++) {
        int b = s & 1;
        int si = s & 15;
        int t = dir ? (T_LEN - 1 - s) : s;

        if (si == 0) {
            int c2 = (s >> 4) + 2;
            if (c2 < (T_LEN / 16)) {
                PRE_ISSUE(c2, c2 % 3);
                asm volatile("cp.async.wait_group 2;" ::: "memory");
            } else {
                asm volatile("cp.async.wait_group 0;" ::: "memory");
            }
            __syncthreads();
        }
        int buf = (s >> 4) % 3;

        // pre for gate cb of this unit (only cb<4 lanes add it)
        float p = (cb < 4) ? pre_s[buf][si][cb * 36 + unit] : 0.f;

        // wait until all 7 remote CTAs delivered h for this step
        if (s > 0) {
            if (b) { mbar_wait(mb1, par1); par1 ^= 1; }
            else   { mbar_wait(mb0, par0); par0 ^= 1; }
        }
        if (tid == 0) mbar_expect_tx(b ? mb1 : mb0, 896);

        // matvec: 4 gate rows x 32 cols; h from hsm[b] block cb
        const ulonglong2* h2 = (const ulonglong2*)(&hsm[b][cb * 36]);
        unsigned long long a0 = 0ull, a1 = 0ull, a2 = 0ull, a3 = 0ull;
#pragma unroll
        for (int q = 0; q < 8; q++) {
            ulonglong2 hv = h2[q];
            a0 = ffma2(wr[0][2 * q], hv.x, a0);
            a1 = ffma2(wr[1][2 * q], hv.x, a1);
            a2 = ffma2(wr[2][2 * q], hv.x, a2);
            a3 = ffma2(wr[3][2 * q], hv.x, a3);
            a0 = ffma2(wr[0][2 * q + 1], hv.y, a0);
            a1 = ffma2(wr[1][2 * q + 1], hv.y, a1);
            a2 = ffma2(wr[2][2 * q + 1], hv.y, a2);
            a3 = ffma2(wr[3][2 * q + 1], hv.y, a3);
        }
        float2 f0 = unpackf2(a0), f1 = unpackf2(a1);
        float2 f2 = unpackf2(a2), f3 = unpackf2(a3);
        float s0 = f0.x + f0.y, s1 = f1.x + f1.y;
        float s2 = f2.x + f2.y, s3 = f3.x + f3.y;

        if (cb == 0) s0 += p;
        else if (cb == 1) s1 += p;
        else if (cb == 2) s2 += p;
        else if (cb == 3) s3 += p;

#pragma unroll
        for (int mk = 1; mk < 8; mk <<= 1) {
            s0 += __shfl_xor_sync(0xffffffffu, s0, mk);
            s1 += __shfl_xor_sync(0xffffffffu, s1, mk);
            s2 += __shfl_xor_sync(0xffffffffu, s2, mk);
            s3 += __shfl_xor_sync(0xffffffffu, s3, mk);
        }

        // gates at cb==0 lanes (4 per warp), one unit each
        if (cb == 0) {
            float ii = sigmoidf_(s0);
            float ff = sigmoidf_(s1);
            float oo = sigmoidf_(s3);
            c = ff * c + ii * tanh_fast(s2);
            float h = oo * tanh_fast(c);
            hstage[b ^ 1][unit] = h;
            hsm[b ^ 1][36 * (int)rank + unit] = h;   // self-delivery (local)
            hout[(size_t)t * H_DIM + k_unit] = h;    // off critical path
        }
        __syncthreads();   // hstage + local hsm staged; hsm[b] reads retired

        // warp 0 lanes 0-7 (minus self): ship 128B block to CTA 'lane'
        if (sender) {
            asm volatile("fence.proxy.async.shared::cta;" ::: "memory");
            uint32_t d = b ? dst_b0 : dst_b1;   // step-s output -> buffer b^1
            uint32_t m = b ? mdst0 : mdst1;
            bulk_s2cluster(d, sbase + (uint32_t)((b ^ 1) * 32) * 4u, 128u, m);
        }
    }

    // drain: final sends (step T-1, odd) targeted mb0; complete that phase
    mbar_wait(mb0, par0);
    asm volatile("barrier.cluster.arrive.aligned;" ::: "memory");
    asm volatile("barrier.cluster.wait.aligned;" ::: "memory");
#undef PRE_ISSUE
}

// ---------------- 3) emit: 16 timesteps per block, W_out SMEM-cached -------
__global__ __launch_bounds__(128) void emit_kernel(
    const float* __restrict__ Wout, const float* __restrict__ bout) {
    int t0 = blockIdx.x * 16;
    __shared__ float Wsm[L_TAGS * 512];     // 36 KB
    __shared__ float h[512];
    __shared__ float part[4][18];
    int tid = threadIdx.x;

    for (int i = tid; i < L_TAGS * 512; i += 128) Wsm[i] = Wout[i];

    for (int tl = 0; tl < 16; tl++) {
        int t = t0 + tl;
        __syncthreads();            // also covers Wsm on first iteration
        h[tid]       = g_h[0][(size_t)t * 256 + tid];
        h[tid + 128] = g_h[0][(size_t)t * 256 + 128 + tid];
        h[tid + 256] = g_h[1][(size_t)t * 256 + tid];
        h[tid + 384] = g_h[1][(size_t)t * 256 + 128 + tid];
        __syncthreads();

        if (tid < 72) {
            int jj = tid >> 2, q = tid & 3;
            const float* w = Wsm + jj * 512 + q * 128;
            const float* hh = h + q * 128;
            float a0 = 0.f, a1 = 0.f, a2 = 0.f, a3 = 0.f;
#pragma unroll
            for (int k = 0; k < 128; k += 4) {
                a0 += hh[k] * w[k];
                a1 += hh[k + 1] * w[k + 1];
                a2 += hh[k + 2] * w[k + 2];
                a3 += hh[k + 3] * w[k + 3];
            }
            part[q][jj] = (a0 + a1) + (a2 + a3);
        }
        __syncthreads();
        if (tid < 18)
            g_emit[(size_t)t * L_TAGS + tid] =
                part[0][tid] + part[1][tid] + part[2][tid] + part[3][tid] +
                bout[tid];
    }
}

// ---------------- 4) Viterbi: max via FMNMX tree, argmax via mask+ffs -------
__global__ void viterbi_kernel(const float* __restrict__ trans,
                               float* __restrict__ out, int write_score) {
    extern __shared__ unsigned char bp[];
    int j = threadIdx.x;
    bool act = (j < L_TAGS);

    float tcol[L_TAGS];
#pragma unroll
    for (int i = 0; i < L_TAGS; i++)
        tcol[i] = act ? trans[i * L_TAGS + j] : 0.f;

    float fv = act ? ((j == START_TAG) ? 0.f : NEGV) : -3.0e38f;
    float e = act ? g_emit[j] : 0.f;

    for (int t = 0; t < T_LEN; t++) {
        float e_next = (act && t + 1 < T_LEN)
                           ? g_emit[(size_t)(t + 1) * L_TAGS + j] : 0.f;
        float sv[L_TAGS];
#pragma unroll
        for (int i = 0; i < L_TAGS; i++)
            sv[i] = __shfl_sync(0xffffffffu, fv, i) + tcol[i];

        // max: parallel fmaxf tree (FMNMX lat 4, no dependent guard chains)
        float m0 = fmaxf(sv[0], sv[1]);
        float m1 = fmaxf(sv[2], sv[3]);
        float m2 = fmaxf(sv[4], sv[5]);
        float m3 = fmaxf(sv[6], sv[7]);
        float m4 = fmaxf(sv[8], sv[9]);
        float m5 = fmaxf(sv[10], sv[11]);
        float m6 = fmaxf(sv[12], sv[13]);
        float m7 = fmaxf(sv[14], sv[15]);
        float m8 = fmaxf(sv[16], sv[17]);
        float n0 = fmaxf(m0, m1);
        float n1 = fmaxf(m2, m3);
        float n2 = fmaxf(m4, m5);
        float n3 = fmaxf(m6, m7);
        float q0 = fmaxf(n0, n1);
        float q1 = fmaxf(n2, n3);
        float best = fmaxf(fmaxf(q0, q1), m8);

        // argmax: first i with sv[i]==best (== jnp.argmax tie semantics)
        unsigned mask = 0;
#pragma unroll
        for (int i = 0; i < L_TAGS; i++)
            mask |= (sv[i] == best) ? (1u << i) : 0u;
        int arg = __ffs(mask) - 1;

        if (act) {
            bp[t * L_TAGS + j] = (unsigned char)arg;
            fv = best + e;
        }
        e = e_next;
    }

    float term = act ? (fv + trans[j * L_TAGS + STOP_TAG]) : -3.4e38f;
    int ai = j;
#pragma unroll
    for (int off = 16; off > 0; off >>= 1) {
        float ov = __shfl_xor_sync(0xffffffffu, term, off);
        int oi = __shfl_xor_sync(0xffffffffu, ai, off);
        if (ov > term || (ov == term && oi < ai)) { term = ov; ai = oi; }
    }

    if (j == 0) {
        if (write_score) out[0] = term;
        float* path = out + write_score;
        int tag = ai;
        for (int t = T_LEN - 1; t >= 0; t--) {
            path[t] = (float)tag;
            tag = bp[t * L_TAGS + tag];
        }
    }
}

// ---------------- launch ----------------------------------------------------
extern "C" void kernel_launch(void* const* d_in, const int* in_sizes, int n_in,
                              void* d_out, int out_size) {
    const int*   feats  = (const int*)d_in[0];
    const float* emb    = (const float*)d_in[1];
    const float* w_ih_f = (const float*)d_in[2];
    const float* w_hh_f = (const float*)d_in[3];
    const float* b_f    = (const float*)d_in[4];
    const float* w_ih_b = (const float*)d_in[5];
    const float* w_hh_b = (const float*)d_in[6];
    const float* b_b    = (const float*)d_in[7];
    const float* W_out  = (const float*)d_in[8];
    const float* b_out  = (const float*)d_in[9];
    const float* trans  = (const float*)d_in[10];

    dim3 gg(G_DIM / 64, T_LEN / 64, 2);
    gemm_pre_kernel<<<gg, 256>>>(feats, emb, w_ih_f, w_ih_b, b_f, b_b);

    lstm_cluster_kernel<<<16, 256>>>(w_hh_f, w_hh_b);

    emit_kernel<<<T_LEN / 16, 128>>>(W_out, b_out);

    int ws = (out_size > T_LEN) ? 1 : 0;   // layout: [path_score, path...]
    static int smem_set = 0;
    if (!smem_set) {
        cudaFuncSetAttribute(viterbi_kernel,
                             cudaFuncAttributeMaxDynamicSharedMemorySize,
                             T_LEN * L_TAGS + 1024);
        smem_set = 1;
    }
    viterbi_kernel<<<1, 32, T_LEN * L_TAGS>>>(trans, (float*)d_out, ws);
}